// round 4
// baseline (speedup 1.0000x reference)
#include <cuda_runtime.h>
#include <cstdint>

#define BB 8
#define SS 1024
#define FEAT 1024
#define HIDD 1024
#define HH 8
#define DHH 128
#define MTOT (BB*SS)

// tf32-rounded copies (bit patterns stored as uint32)
__device__ uint32_t g_Ar[MTOT*FEAT];
__device__ uint32_t g_W0[FEAT*HIDD];
__device__ uint32_t g_W1[FEAT*HIDD];
__device__ uint32_t g_W2[FEAT*HIDD];
__device__ uint32_t g_Q[MTOT*HIDD];
__device__ uint32_t g_K[MTOT*HIDD];
__device__ uint32_t g_V[MTOT*HIDD];

__device__ __forceinline__ uint32_t f2t(float x) {
    uint32_t u;
    asm("cvt.rna.tf32.f32 %0, %1;" : "=r"(u) : "f"(x));
    return u;
}
__device__ __forceinline__ uint32_t smaddr(const void* p) {
    return (uint32_t)__cvta_generic_to_shared(p);
}

#define CP16(dst,src) asm volatile("cp.async.cg.shared.global [%0], [%1], 16;" :: "r"(dst), "l"(src))
#define CPCOMMIT()    asm volatile("cp.async.commit_group;")
#define CPWAIT(n)     asm volatile("cp.async.wait_group %0;" :: "n"(n))

__device__ __forceinline__ void mma8(float* d, const uint32_t* a, const uint32_t* b) {
    asm volatile(
        "mma.sync.aligned.m16n8k8.row.col.f32.tf32.tf32.f32 "
        "{%0,%1,%2,%3}, {%4,%5,%6,%7}, {%8,%9}, {%0,%1,%2,%3};"
        : "+f"(d[0]), "+f"(d[1]), "+f"(d[2]), "+f"(d[3])
        : "r"(a[0]), "r"(a[1]), "r"(a[2]), "r"(a[3]), "r"(b[0]), "r"(b[1]));
}

// ---------------------------------------------------------------------------
// Pass 0: round inputs to tf32 (rna) once, so the GEMM moves raw bits.
// ---------------------------------------------------------------------------
__global__ __launch_bounds__(256)
void round_kernel(const float4* __restrict__ A, const float4* __restrict__ W0,
                  const float4* __restrict__ W1, const float4* __restrict__ W2)
{
    const int NA = MTOT*FEAT/4;
    const int NW = FEAT*HIDD/4;
    int i = blockIdx.x*256 + threadIdx.x;
    if (i < NA) {
        float4 v = A[i];
        ((uint4*)g_Ar)[i] = make_uint4(f2t(v.x), f2t(v.y), f2t(v.z), f2t(v.w));
        return;
    }
    i -= NA;
    if (i < NW) {
        float4 v = W0[i];
        ((uint4*)g_W0)[i] = make_uint4(f2t(v.x), f2t(v.y), f2t(v.z), f2t(v.w));
        return;
    }
    i -= NW;
    if (i < NW) {
        float4 v = W1[i];
        ((uint4*)g_W1)[i] = make_uint4(f2t(v.x), f2t(v.y), f2t(v.z), f2t(v.w));
        return;
    }
    i -= NW;
    if (i < NW) {
        float4 v = W2[i];
        ((uint4*)g_W2)[i] = make_uint4(f2t(v.x), f2t(v.y), f2t(v.z), f2t(v.w));
    }
}

// ---------------------------------------------------------------------------
// Pass 1: QKV projection GEMM, tf32 mma.sync on pre-rounded bits (R2 form).
// ---------------------------------------------------------------------------
#define AS_STR 36
#define WS_STR 132
#define AS_SZ (128*AS_STR)
#define WS_SZ (32*WS_STR)
#define STG   (AS_SZ + WS_SZ)
#define GSM_BYTES (2*STG*4)

__global__ __launch_bounds__(128)
void qkv_mma_kernel(const float* __restrict__ bq, const float* __restrict__ bk,
                    const float* __restrict__ bv)
{
    extern __shared__ uint32_t smg[];
    const int tid = threadIdx.x;
    const int w = tid >> 5, lane = tid & 31;
    const int g = lane >> 2, t = lane & 3;
    const int mw = (w >> 1) * 64, nw = (w & 1) * 64;
    const int row0 = blockIdx.y * 128, col0 = blockIdx.x * 128;

    const uint32_t* Wg = (blockIdx.z == 0) ? g_W0 : (blockIdx.z == 1 ? g_W1 : g_W2);
    const float* bias  = (blockIdx.z == 0) ? bq  : (blockIdx.z == 1 ? bk  : bv);
    uint32_t* Og       = (blockIdx.z == 0) ? g_Q : (blockIdx.z == 1 ? g_K : g_V);

    float acc[4][8][4];
#pragma unroll
    for (int i = 0; i < 4; i++)
#pragma unroll
        for (int j = 0; j < 8; j++)
#pragma unroll
            for (int e = 0; e < 4; e++) acc[i][j][e] = 0.0f;

    auto issue = [&](int it) {
        int st = it & 1;
        uint32_t base = smaddr(smg + st*STG);
        int k0 = it * 32;
#pragma unroll
        for (int c = 0; c < 8; c++) {
            int slot = tid + c*128;
            int r = slot >> 3, kc = (slot & 7) * 4;
            CP16(base + (r*AS_STR + kc)*4, g_Ar + (long)(row0 + r)*FEAT + k0 + kc);
        }
        uint32_t baseW = base + AS_SZ*4;
#pragma unroll
        for (int c = 0; c < 8; c++) {
            int slot = tid + c*128;
            int r = slot >> 5, nc = (slot & 31) * 4;
            CP16(baseW + (r*WS_STR + nc)*4, Wg + (long)(k0 + r)*HIDD + col0 + nc);
        }
    };

    issue(0); CPCOMMIT();
    for (int it = 0; it < 32; ++it) {
        if (it + 1 < 32) issue(it + 1);
        CPCOMMIT();
        CPWAIT(1);
        __syncthreads();
        const uint32_t* As = smg + (it & 1)*STG;
        const uint32_t* Ws = As + AS_SZ;
#pragma unroll
        for (int ks = 0; ks < 4; ks++) {
            uint32_t a[4][4], bfr[8][2];
#pragma unroll
            for (int i = 0; i < 4; i++) {
                const uint32_t* ap = As + (mw + i*16 + g)*AS_STR + ks*8 + t;
                a[i][0] = ap[0];
                a[i][1] = ap[8*AS_STR];
                a[i][2] = ap[4];
                a[i][3] = ap[8*AS_STR + 4];
            }
#pragma unroll
            for (int j = 0; j < 8; j++) {
                const uint32_t* bp = Ws + (ks*8 + t)*WS_STR + nw + j*8 + g;
                bfr[j][0] = bp[0];
                bfr[j][1] = bp[4*WS_STR];
            }
#pragma unroll
            for (int i = 0; i < 4; i++)
#pragma unroll
                for (int j = 0; j < 8; j++)
                    mma8(acc[i][j], a[i], bfr[j]);
        }
        __syncthreads();
    }

#pragma unroll
    for (int j = 0; j < 8; j++) {
        int col = col0 + nw + j*8 + 2*t;
        float b0 = bias[col], b1 = bias[col + 1];
#pragma unroll
        for (int i = 0; i < 4; i++) {
            int row = row0 + mw + i*16 + g;
            uint2 v0 = make_uint2(f2t(acc[i][j][0] + b0), f2t(acc[i][j][1] + b1));
            uint2 v1 = make_uint2(f2t(acc[i][j][2] + b0), f2t(acc[i][j][3] + b1));
            *(uint2*)(Og + (long)row*HIDD + col) = v0;
            *(uint2*)(Og + (long)(row + 8)*HIDD + col) = v1;
        }
    }
}

// ---------------------------------------------------------------------------
// Pass 2: causal attention, tf32 mma.sync, no online max.
// 256 threads, q-tile 128, k-tile 64, double-buffered cp.async.
// K tile stride 132 (conflict-free K-frag loads: bank 4g+t), V tile stride 136
// (conflict-free V-frag loads: bank 8t+g). PV phase warp-split m32 x n64.
// ---------------------------------------------------------------------------
#define K_STR 132
#define V_STR 136
#define PS_STR 68
#define KTILE (64*K_STR)
#define VTILE (64*V_STR)
#define ASTAGE (KTILE + VTILE)
#define PS_OFF (2*ASTAGE)
#define LS_OFF (PS_OFF + 128*PS_STR)
#define ASM_BYTES ((LS_OFF + 128)*4)

__global__ __launch_bounds__(256)
void attn_kernel(float* __restrict__ out)
{
    extern __shared__ uint32_t sm[];
    uint32_t* Ps = sm + PS_OFF;
    float* l_s = (float*)(sm + LS_OFF);

    const int tid = threadIdx.x;
    const int w = tid >> 5, lane = tid & 31;
    const int g = lane >> 2, t = lane & 3;
    const int m0 = w * 16;                 // S-phase rows
    const int mB = (w & 3) * 32;           // PV-phase rows (2 x m16)
    const int nh = (w >> 2) * 64;          // PV-phase col half
    const int qt = 7 - blockIdx.x;
    const int q0 = qt * 128;
    const int bh = blockIdx.y, b = bh >> 3, h = bh & 7;
    const int nk = 2*qt + 2;

    const uint32_t* Qg = g_Q + (long)b*SS*HIDD + h*DHH;
    const uint32_t* Kg = g_K + (long)b*SS*HIDD + h*DHH;
    const uint32_t* Vg = g_V + (long)b*SS*HIDD + h*DHH;

    // stage Q tile [128 x 128] (stride K_STR) through the stage buffers
    {
        uint32_t base = smaddr(sm);
#pragma unroll
        for (int c = 0; c < 16; c++) {
            int slot = tid + c*256;
            int r = slot >> 5, cc = (slot & 31) * 4;
            CP16(base + (r*K_STR + cc)*4, Qg + (long)(q0 + r)*HIDD + cc);
        }
        CPCOMMIT(); CPWAIT(0);
    }
    __syncthreads();

    uint32_t aQ[16][4];
#pragma unroll
    for (int ks = 0; ks < 16; ks++) {
        const uint32_t* qp = sm + (m0 + g)*K_STR + ks*8 + t;
        aQ[ks][0] = qp[0];
        aQ[ks][1] = qp[8*K_STR];
        aQ[ks][2] = qp[4];
        aQ[ks][3] = qp[8*K_STR + 4];
    }
    __syncthreads();

    float accO[2][8][4];
#pragma unroll
    for (int mi = 0; mi < 2; mi++)
#pragma unroll
        for (int j = 0; j < 8; j++)
#pragma unroll
            for (int e = 0; e < 4; e++) accO[mi][j][e] = 0.0f;
    float l0 = 0.0f, l1 = 0.0f;
    const float scl = 0.08838834764831843f;

    auto issue = [&](int kt) {
        uint32_t baseK = smaddr(sm + (kt & 1)*ASTAGE);
        uint32_t baseV = baseK + KTILE*4;
        int k0 = kt * 64;
#pragma unroll
        for (int c = 0; c < 8; c++) {
            int slot = tid + c*256;
            int r = slot >> 5, cc = (slot & 31) * 4;
            CP16(baseK + (r*K_STR + cc)*4, Kg + (long)(k0 + r)*HIDD + cc);
            CP16(baseV + (r*V_STR + cc)*4, Vg + (long)(k0 + r)*HIDD + cc);
        }
    };

    issue(0); CPCOMMIT();
    for (int kt = 0; kt < nk; kt++) {
        if (kt + 1 < nk) issue(kt + 1);
        CPCOMMIT();
        CPWAIT(1);
        __syncthreads();
        const uint32_t* Ks = sm + (kt & 1)*ASTAGE;
        const uint32_t* Vs = Ks + KTILE;
        const int k0 = kt * 64;

        // blocks j with k0+8j > q0+m0+15 are fully masked -> skip
        const int mrow_max = q0 + m0 + 15;
        const int jlim = (k0 > mrow_max) ? 0
                        : min(8, ((mrow_max - k0) >> 3) + 1);

        float s[8][4];
#pragma unroll
        for (int j = 0; j < 8; j++)
#pragma unroll
            for (int e = 0; e < 4; e++) s[j][e] = 0.0f;

#pragma unroll
        for (int ks = 0; ks < 16; ks++) {
            for (int j = 0; j < jlim; j++) {
                uint32_t bfr[2];
                const uint32_t* kp = Ks + (j*8 + g)*K_STR + ks*8 + t;
                bfr[0] = kp[0];
                bfr[1] = kp[4];
                mma8(s[j], aQ[ks], bfr);
            }
        }

        // p = exp(exp(s/sqrt(d))), causal mask on near-diagonal tiles
        const int row_g  = q0 + m0 + g;
        const int row_g8 = row_g + 8;
        const bool diag = (k0 + 63 > row_g);
#pragma unroll
        for (int j = 0; j < 8; j++) {
            uint32_t u0 = 0, u1 = 0, u2 = 0, u3 = 0;
            if (j < jlim) {
                int c0 = k0 + j*8 + 2*t;
                float y0 = __expf(s[j][0]*scl), y1 = __expf(s[j][1]*scl);
                float y2 = __expf(s[j][2]*scl), y3 = __expf(s[j][3]*scl);
                float p0 = __expf(y0), p1 = __expf(y1);
                float p2 = __expf(y2), p3 = __expf(y3);
                if (diag) {
                    if (c0     > row_g ) p0 = 0.0f;
                    if (c0 + 1 > row_g ) p1 = 0.0f;
                    if (c0     > row_g8) p2 = 0.0f;
                    if (c0 + 1 > row_g8) p3 = 0.0f;
                }
                u0 = f2t(p0); u1 = f2t(p1); u2 = f2t(p2); u3 = f2t(p3);
                l0 += __uint_as_float(u0) + __uint_as_float(u1);
                l1 += __uint_as_float(u2) + __uint_as_float(u3);
            }
            *(uint2*)(Ps + (m0 + g)*PS_STR + j*8 + 2*t)     = make_uint2(u0, u1);
            *(uint2*)(Ps + (m0 + g + 8)*PS_STR + j*8 + 2*t) = make_uint2(u2, u3);
        }
        __syncthreads();

        // O += P V : warp tile m32 (rows mB..mB+31) x n64 (cols nh..nh+63)
#pragma unroll
        for (int ks = 0; ks < 8; ks++) {
            uint32_t aP[2][4];
#pragma unroll
            for (int mi = 0; mi < 2; mi++) {
                const uint32_t* pp = Ps + (mB + mi*16 + g)*PS_STR + ks*8 + t;
                aP[mi][0] = pp[0];
                aP[mi][1] = pp[8*PS_STR];
                aP[mi][2] = pp[4];
                aP[mi][3] = pp[8*PS_STR + 4];
            }
#pragma unroll
            for (int j = 0; j < 8; j++) {
                uint32_t bfr[2];
                const uint32_t* vp = Vs + (ks*8 + t)*V_STR + nh + j*8 + g;
                bfr[0] = vp[0];
                bfr[1] = vp[4*V_STR];
                mma8(accO[0][j], aP[0], bfr);
                mma8(accO[1][j], aP[1], bfr);
            }
        }
        __syncthreads();
    }

    // publish row sums (S-phase rows), then normalize PV rows
    l0 += __shfl_xor_sync(0xffffffffu, l0, 1);
    l0 += __shfl_xor_sync(0xffffffffu, l0, 2);
    l1 += __shfl_xor_sync(0xffffffffu, l1, 1);
    l1 += __shfl_xor_sync(0xffffffffu, l1, 2);
    if (t == 0) {
        l_s[m0 + g]     = l0;
        l_s[m0 + g + 8] = l1;
    }
    __syncthreads();

#pragma unroll
    for (int mi = 0; mi < 2; mi++) {
        const int r = mB + mi*16 + g;
        const float ra = 1.0f / l_s[r];
        const float rb = 1.0f / l_s[r + 8];
        float* outp = out + ((long)b*SS + q0 + r)*HIDD + h*DHH + nh;
#pragma unroll
        for (int j = 0; j < 8; j++) {
            int col = j*8 + 2*t;
            *(float2*)(outp + col)          = make_float2(accO[mi][j][0]*ra, accO[mi][j][1]*ra);
            *(float2*)(outp + 8*HIDD + col) = make_float2(accO[mi][j][2]*rb, accO[mi][j][3]*rb);
        }
    }
}

// ---------------------------------------------------------------------------
extern "C" void kernel_launch(void* const* d_in, const int* in_sizes, int n_in,
                              void* d_out, int out_size)
{
    const float* queries = (const float*)d_in[0];
    const float* Wq = (const float*)d_in[1];
    const float* bq = (const float*)d_in[2];
    const float* Wk = (const float*)d_in[3];
    const float* bk = (const float*)d_in[4];
    const float* Wv = (const float*)d_in[5];
    const float* bv = (const float*)d_in[6];
    float* out = (float*)d_out;

    cudaFuncSetAttribute(qkv_mma_kernel, cudaFuncAttributeMaxDynamicSharedMemorySize, GSM_BYTES);
    cudaFuncSetAttribute(attn_kernel, cudaFuncAttributeMaxDynamicSharedMemorySize, ASM_BYTES);

    round_kernel<<<11264, 256>>>((const float4*)queries, (const float4*)Wq,
                                 (const float4*)Wk, (const float4*)Wv);
    qkv_mma_kernel<<<dim3(8, 64, 3), 128, GSM_BYTES>>>(bq, bk, bv);
    attn_kernel<<<dim3(8, 64), 256, ASM_BYTES>>>(out);
}

// round 5
// speedup vs baseline: 1.5237x; 1.5237x over previous
#include <cuda_runtime.h>
#include <cstdint>

#define BB 8
#define SS 1024
#define FEAT 1024
#define HIDD 1024
#define HH 8
#define DHH 128
#define MTOT (BB*SS)

// tf32-rounded copies (bit patterns stored as uint32)
__device__ uint32_t g_Ar[MTOT*FEAT];
__device__ uint32_t g_W0[FEAT*HIDD];
__device__ uint32_t g_W1[FEAT*HIDD];
__device__ uint32_t g_W2[FEAT*HIDD];
__device__ uint32_t g_Q[MTOT*HIDD];
__device__ uint32_t g_K[MTOT*HIDD];
__device__ uint32_t g_V[MTOT*HIDD];

__device__ __forceinline__ uint32_t f2t(float x) {
    uint32_t u;
    asm("cvt.rna.tf32.f32 %0, %1;" : "=r"(u) : "f"(x));
    return u;
}
__device__ __forceinline__ uint32_t smaddr(const void* p) {
    return (uint32_t)__cvta_generic_to_shared(p);
}

#define CP16(dst,src) asm volatile("cp.async.cg.shared.global [%0], [%1], 16;" :: "r"(dst), "l"(src))
#define CPCOMMIT()    asm volatile("cp.async.commit_group;")
#define CPWAIT(n)     asm volatile("cp.async.wait_group %0;" :: "n"(n))

__device__ __forceinline__ void mma8(float* d, const uint32_t* a, const uint32_t* b) {
    asm volatile(
        "mma.sync.aligned.m16n8k8.row.col.f32.tf32.tf32.f32 "
        "{%0,%1,%2,%3}, {%4,%5,%6,%7}, {%8,%9}, {%0,%1,%2,%3};"
        : "+f"(d[0]), "+f"(d[1]), "+f"(d[2]), "+f"(d[3])
        : "r"(a[0]), "r"(a[1]), "r"(a[2]), "r"(a[3]), "r"(b[0]), "r"(b[1]));
}

// ---------------------------------------------------------------------------
// Pass 0: round inputs to tf32 (rna) once, so the GEMM moves raw bits.
// ---------------------------------------------------------------------------
__global__ __launch_bounds__(256)
void round_kernel(const float4* __restrict__ A, const float4* __restrict__ W0,
                  const float4* __restrict__ W1, const float4* __restrict__ W2)
{
    const int NA = MTOT*FEAT/4;
    const int NW = FEAT*HIDD/4;
    int i = blockIdx.x*256 + threadIdx.x;
    if (i < NA) {
        float4 v = A[i];
        ((uint4*)g_Ar)[i] = make_uint4(f2t(v.x), f2t(v.y), f2t(v.z), f2t(v.w));
        return;
    }
    i -= NA;
    if (i < NW) {
        float4 v = W0[i];
        ((uint4*)g_W0)[i] = make_uint4(f2t(v.x), f2t(v.y), f2t(v.z), f2t(v.w));
        return;
    }
    i -= NW;
    if (i < NW) {
        float4 v = W1[i];
        ((uint4*)g_W1)[i] = make_uint4(f2t(v.x), f2t(v.y), f2t(v.z), f2t(v.w));
        return;
    }
    i -= NW;
    if (i < NW) {
        float4 v = W2[i];
        ((uint4*)g_W2)[i] = make_uint4(f2t(v.x), f2t(v.y), f2t(v.z), f2t(v.w));
    }
}

// ---------------------------------------------------------------------------
// Pass 1: QKV projection GEMM, tf32 mma.sync on pre-rounded bits (R2 form).
// ---------------------------------------------------------------------------
#define AS_STR 36
#define WS_STR 132
#define AS_SZ (128*AS_STR)
#define WS_SZ (32*WS_STR)
#define STG   (AS_SZ + WS_SZ)
#define GSM_BYTES (2*STG*4)

__global__ __launch_bounds__(128)
void qkv_mma_kernel(const float* __restrict__ bq, const float* __restrict__ bk,
                    const float* __restrict__ bv)
{
    extern __shared__ uint32_t smg[];
    const int tid = threadIdx.x;
    const int w = tid >> 5, lane = tid & 31;
    const int g = lane >> 2, t = lane & 3;
    const int mw = (w >> 1) * 64, nw = (w & 1) * 64;
    const int row0 = blockIdx.y * 128, col0 = blockIdx.x * 128;

    const uint32_t* Wg = (blockIdx.z == 0) ? g_W0 : (blockIdx.z == 1 ? g_W1 : g_W2);
    const float* bias  = (blockIdx.z == 0) ? bq  : (blockIdx.z == 1 ? bk  : bv);
    uint32_t* Og       = (blockIdx.z == 0) ? g_Q : (blockIdx.z == 1 ? g_K : g_V);

    float acc[4][8][4];
#pragma unroll
    for (int i = 0; i < 4; i++)
#pragma unroll
        for (int j = 0; j < 8; j++)
#pragma unroll
            for (int e = 0; e < 4; e++) acc[i][j][e] = 0.0f;

    auto issue = [&](int it) {
        int st = it & 1;
        uint32_t base = smaddr(smg + st*STG);
        int k0 = it * 32;
#pragma unroll
        for (int c = 0; c < 8; c++) {
            int slot = tid + c*128;
            int r = slot >> 3, kc = (slot & 7) * 4;
            CP16(base + (r*AS_STR + kc)*4, g_Ar + (long)(row0 + r)*FEAT + k0 + kc);
        }
        uint32_t baseW = base + AS_SZ*4;
#pragma unroll
        for (int c = 0; c < 8; c++) {
            int slot = tid + c*128;
            int r = slot >> 5, nc = (slot & 31) * 4;
            CP16(baseW + (r*WS_STR + nc)*4, Wg + (long)(k0 + r)*HIDD + col0 + nc);
        }
    };

    issue(0); CPCOMMIT();
    for (int it = 0; it < 32; ++it) {
        if (it + 1 < 32) issue(it + 1);
        CPCOMMIT();
        CPWAIT(1);
        __syncthreads();
        const uint32_t* As = smg + (it & 1)*STG;
        const uint32_t* Ws = As + AS_SZ;
#pragma unroll
        for (int ks = 0; ks < 4; ks++) {
            uint32_t a[4][4], bfr[8][2];
#pragma unroll
            for (int i = 0; i < 4; i++) {
                const uint32_t* ap = As + (mw + i*16 + g)*AS_STR + ks*8 + t;
                a[i][0] = ap[0];
                a[i][1] = ap[8*AS_STR];
                a[i][2] = ap[4];
                a[i][3] = ap[8*AS_STR + 4];
            }
#pragma unroll
            for (int j = 0; j < 8; j++) {
                const uint32_t* bp = Ws + (ks*8 + t)*WS_STR + nw + j*8 + g;
                bfr[j][0] = bp[0];
                bfr[j][1] = bp[4*WS_STR];
            }
#pragma unroll
            for (int i = 0; i < 4; i++)
#pragma unroll
                for (int j = 0; j < 8; j++)
                    mma8(acc[i][j], a[i], bfr[j]);
        }
        __syncthreads();
    }

#pragma unroll
    for (int j = 0; j < 8; j++) {
        int col = col0 + nw + j*8 + 2*t;
        float b0 = bias[col], b1 = bias[col + 1];
#pragma unroll
        for (int i = 0; i < 4; i++) {
            int row = row0 + mw + i*16 + g;
            uint2 v0 = make_uint2(f2t(acc[i][j][0] + b0), f2t(acc[i][j][1] + b1));
            uint2 v1 = make_uint2(f2t(acc[i][j][2] + b0), f2t(acc[i][j][3] + b1));
            *(uint2*)(Og + (long)row*HIDD + col) = v0;
            *(uint2*)(Og + (long)(row + 8)*HIDD + col) = v1;
        }
    }
}

// ---------------------------------------------------------------------------
// Pass 2: causal attention (R3 form, measured 216.8us).
// 256 threads (8 warps x 16 q-rows), q-tile 128, k-tile 64,
// double-buffered cp.async K/V pipeline, fully static unrolled loops.
// ---------------------------------------------------------------------------
#define KV_STR 132
#define PS_STR 68
#define KVTILE (64*KV_STR)
#define ASTAGE (2*KVTILE)
#define PS_OFF (2*ASTAGE)
#define ASM_BYTES ((2*ASTAGE + 128*PS_STR)*4)

__global__ __launch_bounds__(256)
void attn_kernel(float* __restrict__ out)
{
    extern __shared__ uint32_t sm[];
    uint32_t* Ps = sm + PS_OFF;

    const int tid = threadIdx.x;
    const int w = tid >> 5, lane = tid & 31;
    const int g = lane >> 2, t = lane & 3;
    const int m0 = w * 16;
    const int qt = 7 - blockIdx.x;
    const int q0 = qt * 128;
    const int bh = blockIdx.y, b = bh >> 3, h = bh & 7;
    const int nk = 2*qt + 2;

    const uint32_t* Qg = g_Q + (long)b*SS*HIDD + h*DHH;
    const uint32_t* Kg = g_K + (long)b*SS*HIDD + h*DHH;
    const uint32_t* Vg = g_V + (long)b*SS*HIDD + h*DHH;

    {
        uint32_t base = smaddr(sm);
#pragma unroll
        for (int c = 0; c < 16; c++) {
            int slot = tid + c*256;
            int r = slot >> 5, cc = (slot & 31) * 4;
            CP16(base + (r*KV_STR + cc)*4, Qg + (long)(q0 + r)*HIDD + cc);
        }
        CPCOMMIT(); CPWAIT(0);
    }
    __syncthreads();

    uint32_t aQ[16][4];
#pragma unroll
    for (int ks = 0; ks < 16; ks++) {
        const uint32_t* qp = sm + (m0 + g)*KV_STR + ks*8 + t;
        aQ[ks][0] = qp[0];
        aQ[ks][1] = qp[8*KV_STR];
        aQ[ks][2] = qp[4];
        aQ[ks][3] = qp[8*KV_STR + 4];
    }
    __syncthreads();

    float accO[16][4];
#pragma unroll
    for (int j = 0; j < 16; j++)
#pragma unroll
        for (int e = 0; e < 4; e++) accO[j][e] = 0.0f;
    float l0 = 0.0f, l1 = 0.0f;
    const float scl = 0.08838834764831843f;

    auto issue = [&](int kt) {
        uint32_t base = smaddr(sm + (kt & 1)*ASTAGE);
        int k0 = kt * 64;
#pragma unroll
        for (int c = 0; c < 8; c++) {
            int slot = tid + c*256;
            int r = slot >> 5, cc = (slot & 31) * 4;
            CP16(base + (r*KV_STR + cc)*4, Kg + (long)(k0 + r)*HIDD + cc);
            CP16(base + (KVTILE + r*KV_STR + cc)*4, Vg + (long)(k0 + r)*HIDD + cc);
        }
    };

    issue(0); CPCOMMIT();
    for (int kt = 0; kt < nk; kt++) {
        if (kt + 1 < nk) issue(kt + 1);
        CPCOMMIT();
        CPWAIT(1);
        __syncthreads();
        const uint32_t* Ks = sm + (kt & 1)*ASTAGE;
        const uint32_t* Vs = Ks + KVTILE;
        const int k0 = kt * 64;

        float s[8][4];
#pragma unroll
        for (int j = 0; j < 8; j++)
#pragma unroll
            for (int e = 0; e < 4; e++) s[j][e] = 0.0f;
#pragma unroll
        for (int ks = 0; ks < 16; ks++) {
#pragma unroll
            for (int j = 0; j < 8; j++) {
                uint32_t bfr[2];
                const uint32_t* kp = Ks + (j*8 + g)*KV_STR + ks*8 + t;
                bfr[0] = kp[0];
                bfr[1] = kp[4];
                mma8(s[j], aQ[ks], bfr);
            }
        }

        const int row_g  = q0 + m0 + g;
        const int row_g8 = row_g + 8;
        const bool diag = (k0 + 63 > row_g);
#pragma unroll
        for (int j = 0; j < 8; j++) {
            int c0 = k0 + j*8 + 2*t;
            float y0 = __expf(s[j][0]*scl), y1 = __expf(s[j][1]*scl);
            float y2 = __expf(s[j][2]*scl), y3 = __expf(s[j][3]*scl);
            float p0 = __expf(y0), p1 = __expf(y1);
            float p2 = __expf(y2), p3 = __expf(y3);
            if (diag) {
                if (c0     > row_g ) p0 = 0.0f;
                if (c0 + 1 > row_g ) p1 = 0.0f;
                if (c0     > row_g8) p2 = 0.0f;
                if (c0 + 1 > row_g8) p3 = 0.0f;
            }
            uint32_t u0 = f2t(p0), u1 = f2t(p1), u2 = f2t(p2), u3 = f2t(p3);
            l0 += __uint_as_float(u0) + __uint_as_float(u1);
            l1 += __uint_as_float(u2) + __uint_as_float(u3);
            *(uint2*)(Ps + (m0 + g)*PS_STR + j*8 + 2*t)     = make_uint2(u0, u1);
            *(uint2*)(Ps + (m0 + g + 8)*PS_STR + j*8 + 2*t) = make_uint2(u2, u3);
        }
        __syncwarp();

#pragma unroll
        for (int ks = 0; ks < 8; ks++) {
            uint32_t aP[4];
            const uint32_t* pp = Ps + (m0 + g)*PS_STR + ks*8 + t;
            aP[0] = pp[0];
            aP[1] = pp[8*PS_STR];
            aP[2] = pp[4];
            aP[3] = pp[8*PS_STR + 4];
#pragma unroll
            for (int j = 0; j < 16; j++) {
                uint32_t bfr[2];
                const uint32_t* vp = Vs + (ks*8 + t)*KV_STR + j*8 + g;
                bfr[0] = vp[0];
                bfr[1] = vp[4*KV_STR];
                mma8(accO[j], aP, bfr);
            }
        }
        __syncthreads();
    }

    l0 += __shfl_xor_sync(0xffffffffu, l0, 1);
    l0 += __shfl_xor_sync(0xffffffffu, l0, 2);
    l1 += __shfl_xor_sync(0xffffffffu, l1, 1);
    l1 += __shfl_xor_sync(0xffffffffu, l1, 2);
    const float r0 = 1.0f / l0, r1 = 1.0f / l1;

    float* outp = out + ((long)b*SS + q0 + m0 + g)*HIDD + h*DHH;
#pragma unroll
    for (int j = 0; j < 16; j++) {
        int col = j*8 + 2*t;
        *(float2*)(outp + col)          = make_float2(accO[j][0]*r0, accO[j][1]*r0);
        *(float2*)(outp + 8*HIDD + col) = make_float2(accO[j][2]*r1, accO[j][3]*r1);
    }
}

// ---------------------------------------------------------------------------
extern "C" void kernel_launch(void* const* d_in, const int* in_sizes, int n_in,
                              void* d_out, int out_size)
{
    const float* queries = (const float*)d_in[0];
    const float* Wq = (const float*)d_in[1];
    const float* bq = (const float*)d_in[2];
    const float* Wk = (const float*)d_in[3];
    const float* bk = (const float*)d_in[4];
    const float* Wv = (const float*)d_in[5];
    const float* bv = (const float*)d_in[6];
    float* out = (float*)d_out;

    cudaFuncSetAttribute(qkv_mma_kernel, cudaFuncAttributeMaxDynamicSharedMemorySize, GSM_BYTES);
    cudaFuncSetAttribute(attn_kernel, cudaFuncAttributeMaxDynamicSharedMemorySize, ASM_BYTES);

    round_kernel<<<11264, 256>>>((const float4*)queries, (const float4*)Wq,
                                 (const float4*)Wk, (const float4*)Wv);
    qkv_mma_kernel<<<dim3(8, 64, 3), 128, GSM_BYTES>>>(bq, bk, bv);
    attn_kernel<<<dim3(8, 64), 256, ASM_BYTES>>>(out);
}

// round 7
// speedup vs baseline: 1.7060x; 1.1196x over previous
#include <cuda_runtime.h>
#include <cstdint>

#define BB 8
#define SS 1024
#define FEAT 1024
#define HIDD 1024
#define HH 8
#define DHH 128
#define MTOT (BB*SS)

// fragment-permuted tf32 operands for the QKV GEMM
// Aperm: [mblk(512)][ks(128)][lane(32)][4]  (A-fragment of m16k8 block per lane)
// Wperm: [z][jp(64)][ks(128)][lane(32)][4]  (B-fragments of two n8 blocks per lane)
__device__ uint32_t g_Ap[MTOT/16 * FEAT/8 * 32 * 4];
__device__ uint32_t g_Wp[3][HIDD/16 * FEAT/8 * 32 * 4];
// tf32-rounded Q/K/V (bit patterns), consumed by attention
__device__ uint32_t g_Q[MTOT*HIDD];
__device__ uint32_t g_K[MTOT*HIDD];
__device__ uint32_t g_V[MTOT*HIDD];

__device__ __forceinline__ uint32_t f2t(float x) {
    uint32_t u;
    asm("cvt.rna.tf32.f32 %0, %1;" : "=r"(u) : "f"(x));
    return u;
}
__device__ __forceinline__ uint32_t smaddr(const void* p) {
    return (uint32_t)__cvta_generic_to_shared(p);
}

#define CP16(dst,src) asm volatile("cp.async.cg.shared.global [%0], [%1], 16;" :: "r"(dst), "l"(src))
#define CPCOMMIT()    asm volatile("cp.async.commit_group;")
#define CPWAIT(n)     asm volatile("cp.async.wait_group %0;" :: "n"(n))

__device__ __forceinline__ void mma8(float* d, const uint32_t* a, const uint32_t* b) {
    asm volatile(
        "mma.sync.aligned.m16n8k8.row.col.f32.tf32.tf32.f32 "
        "{%0,%1,%2,%3}, {%4,%5,%6,%7}, {%8,%9}, {%0,%1,%2,%3};"
        : "+f"(d[0]), "+f"(d[1]), "+f"(d[2]), "+f"(d[3])
        : "r"(a[0]), "r"(a[1]), "r"(a[2]), "r"(a[3]), "r"(b[0]), "r"(b[1]));
}

// ---------------------------------------------------------------------------
// Prep A: queries -> tf32 bits in fragment-permuted order.
// One thread per (mblk, ks, lane) 16B chunk.
// ---------------------------------------------------------------------------
__global__ __launch_bounds__(256)
void prep_a_kernel(const float* __restrict__ A)
{
    int idx = blockIdx.x*256 + threadIdx.x;      // 0 .. 512*128*32-1
    int lane = idx & 31;
    int ks   = (idx >> 5) & 127;
    int mblk = idx >> 12;
    int g = lane >> 2, t = lane & 3;
    int row = 16*mblk + g, col = 8*ks + t;
    const float* p0 = A + (long)row*FEAT + col;
    const float* p1 = A + (long)(row + 8)*FEAT + col;
    uint4 o;
    o.x = f2t(p0[0]);
    o.y = f2t(p1[0]);
    o.z = f2t(p0[4]);
    o.w = f2t(p1[4]);
    *(uint4*)(g_Ap + (long)idx*4) = o;
}

// ---------------------------------------------------------------------------
// Prep W: weights -> tf32 bits, b-fragments of two n8 blocks packed per lane.
// ---------------------------------------------------------------------------
__global__ __launch_bounds__(256)
void prep_w_kernel(const float* __restrict__ W0, const float* __restrict__ W1,
                   const float* __restrict__ W2)
{
    const float* W = (blockIdx.z == 0) ? W0 : (blockIdx.z == 1 ? W1 : W2);
    int idx = blockIdx.x*256 + threadIdx.x;      // 0 .. 64*128*32-1
    int lane = idx & 31;
    int ks   = (idx >> 5) & 127;
    int jp   = idx >> 12;
    int g = lane >> 2, t = lane & 3;
    int kr = 8*ks + t;
    int n0 = 16*jp + g;
    uint4 o;
    o.x = f2t(W[(long)kr*HIDD + n0]);            // j=2jp   b0 (k=t,  n=g)
    o.y = f2t(W[(long)(kr + 4)*HIDD + n0]);      // j=2jp   b1 (k=t+4,n=g)
    o.z = f2t(W[(long)kr*HIDD + n0 + 8]);        // j=2jp+1 b0
    o.w = f2t(W[(long)(kr + 4)*HIDD + n0 + 8]);  // j=2jp+1 b1
    *(uint4*)(g_Wp[blockIdx.z] + (long)idx*4) = o;
}

// ---------------------------------------------------------------------------
// Pass 1: QKV projection GEMM, tf32 mma.sync, fragment-permuted smem:
// every fragment load is one conflict-free LDS.128.
// 128 threads (4 warps, 64x64), block tile 128x128, K-step 32, double buffer.
// Smem per stage: A 16KB + B 16KB.
// ---------------------------------------------------------------------------
#define QSTG_W 8192                     // words per stage (A 4096 + B 4096)
#define GSM_BYTES (2*QSTG_W*4)          // 65536

__global__ __launch_bounds__(128)
void qkv_mma_kernel(const float* __restrict__ bq, const float* __restrict__ bk,
                    const float* __restrict__ bv)
{
    extern __shared__ uint32_t smg[];
    const int tid = threadIdx.x;
    const int w = tid >> 5, lane = tid & 31;
    const int g = lane >> 2, t = lane & 3;
    const int mw = (w >> 1) * 64, nw = (w & 1) * 64;   // warp tile origin
    const int row0 = blockIdx.y * 128, col0 = blockIdx.x * 128;
    const int mb0 = row0 >> 4, jp0 = col0 >> 4;        // global block indices

    const uint32_t* Wp = g_Wp[blockIdx.z];
    const float* bias  = (blockIdx.z == 0) ? bq  : (blockIdx.z == 1 ? bk  : bv);
    uint32_t* Og       = (blockIdx.z == 0) ? g_Q : (blockIdx.z == 1 ? g_K : g_V);

    float acc[4][8][4];
#pragma unroll
    for (int i = 0; i < 4; i++)
#pragma unroll
        for (int j = 0; j < 8; j++)
#pragma unroll
            for (int e = 0; e < 4; e++) acc[i][j][e] = 0.0f;

    // fill stage: A chunks c=0..1023: mblk_loc=c>>7, ks_loc=(c>>5)&3, lane_c=c&31
    auto issue = [&](int it) {
        uint32_t base = smaddr(smg + (it & 1)*QSTG_W);
        int ks0 = it * 4;                       // global ks base (K-step 32 = 4 ks)
#pragma unroll
        for (int i = 0; i < 8; i++) {
            int c = tid + i*128;                // 0..1023
            int mloc = c >> 7, ksl = (c >> 5) & 3, lc = c & 31;
            CP16(base + c*16,
                 g_Ap + (((long)(mb0 + mloc)*128 + ks0 + ksl)*32 + lc)*4);
        }
        uint32_t baseB = base + 4096*4;
#pragma unroll
        for (int i = 0; i < 8; i++) {
            int c = tid + i*128;
            int jloc = c >> 7, ksl = (c >> 5) & 3, lc = c & 31;
            CP16(baseB + c*16,
                 Wp + (((long)(jp0 + jloc)*128 + ks0 + ksl)*32 + lc)*4);
        }
    };

    issue(0); CPCOMMIT();
    for (int it = 0; it < 32; ++it) {
        if (it + 1 < 32) issue(it + 1);
        CPCOMMIT();
        CPWAIT(1);
        __syncthreads();
        const uint32_t* As = smg + (it & 1)*QSTG_W;
        const uint32_t* Bs = As + 4096;
#pragma unroll
        for (int ks = 0; ks < 4; ks++) {
            uint32_t a[4][4], b[4][4];
#pragma unroll
            for (int i = 0; i < 4; i++) {
                int mloc = (mw >> 4) + i;
                *(uint4*)a[i] = *(const uint4*)(As + ((mloc*4 + ks)*32 + lane)*4);
            }
#pragma unroll
            for (int jp = 0; jp < 4; jp++) {
                int jloc = (nw >> 4) + jp;
                *(uint4*)b[jp] = *(const uint4*)(Bs + ((jloc*4 + ks)*32 + lane)*4);
            }
#pragma unroll
            for (int i = 0; i < 4; i++)
#pragma unroll
                for (int jp = 0; jp < 4; jp++) {
                    mma8(acc[i][2*jp],     a[i], &b[jp][0]);
                    mma8(acc[i][2*jp + 1], a[i], &b[jp][2]);
                }
        }
        __syncthreads();
    }

    // epilogue: + bias, round to tf32, store bits (same as R2)
#pragma unroll
    for (int j = 0; j < 8; j++) {
        int col = col0 + nw + j*8 + 2*t;
        float b0 = bias[col], b1 = bias[col + 1];
#pragma unroll
        for (int i = 0; i < 4; i++) {
            int row = row0 + mw + i*16 + g;
            uint2 v0 = make_uint2(f2t(acc[i][j][0] + b0), f2t(acc[i][j][1] + b1));
            uint2 v1 = make_uint2(f2t(acc[i][j][2] + b0), f2t(acc[i][j][3] + b1));
            *(uint2*)(Og + (long)row*HIDD + col) = v0;
            *(uint2*)(Og + (long)(row + 8)*HIDD + col) = v1;
        }
    }
}

// ---------------------------------------------------------------------------
// Pass 2: causal attention (R3/R5 form, measured 216.8us). UNCHANGED.
// ---------------------------------------------------------------------------
#define KV_STR 132
#define PS_STR 68
#define KVTILE (64*KV_STR)
#define ASTAGE (2*KVTILE)
#define PS_OFF (2*ASTAGE)
#define ASM_BYTES ((2*ASTAGE + 128*PS_STR)*4)

__global__ __launch_bounds__(256)
void attn_kernel(float* __restrict__ out)
{
    extern __shared__ uint32_t sm[];
    uint32_t* Ps = sm + PS_OFF;

    const int tid = threadIdx.x;
    const int w = tid >> 5, lane = tid & 31;
    const int g = lane >> 2, t = lane & 3;
    const int m0 = w * 16;
    const int qt = 7 - blockIdx.x;
    const int q0 = qt * 128;
    const int bh = blockIdx.y, b = bh >> 3, h = bh & 7;
    const int nk = 2*qt + 2;

    const uint32_t* Qg = g_Q + (long)b*SS*HIDD + h*DHH;
    const uint32_t* Kg = g_K + (long)b*SS*HIDD + h*DHH;
    const uint32_t* Vg = g_V + (long)b*SS*HIDD + h*DHH;

    {
        uint32_t base = smaddr(sm);
#pragma unroll
        for (int c = 0; c < 16; c++) {
            int slot = tid + c*256;
            int r = slot >> 5, cc = (slot & 31) * 4;
            CP16(base + (r*KV_STR + cc)*4, Qg + (long)(q0 + r)*HIDD + cc);
        }
        CPCOMMIT(); CPWAIT(0);
    }
    __syncthreads();

    uint32_t aQ[16][4];
#pragma unroll
    for (int ks = 0; ks < 16; ks++) {
        const uint32_t* qp = sm + (m0 + g)*KV_STR + ks*8 + t;
        aQ[ks][0] = qp[0];
        aQ[ks][1] = qp[8*KV_STR];
        aQ[ks][2] = qp[4];
        aQ[ks][3] = qp[8*KV_STR + 4];
    }
    __syncthreads();

    float accO[16][4];
#pragma unroll
    for (int j = 0; j < 16; j++)
#pragma unroll
        for (int e = 0; e < 4; e++) accO[j][e] = 0.0f;
    float l0 = 0.0f, l1 = 0.0f;
    const float scl = 0.08838834764831843f;

    auto issue = [&](int kt) {
        uint32_t base = smaddr(sm + (kt & 1)*ASTAGE);
        int k0 = kt * 64;
#pragma unroll
        for (int c = 0; c < 8; c++) {
            int slot = tid + c*256;
            int r = slot >> 5, cc = (slot & 31) * 4;
            CP16(base + (r*KV_STR + cc)*4, Kg + (long)(k0 + r)*HIDD + cc);
            CP16(base + (KVTILE + r*KV_STR + cc)*4, Vg + (long)(k0 + r)*HIDD + cc);
        }
    };

    issue(0); CPCOMMIT();
    for (int kt = 0; kt < nk; kt++) {
        if (kt + 1 < nk) issue(kt + 1);
        CPCOMMIT();
        CPWAIT(1);
        __syncthreads();
        const uint32_t* Ks = sm + (kt & 1)*ASTAGE;
        const uint32_t* Vs = Ks + KVTILE;
        const int k0 = kt * 64;

        float s[8][4];
#pragma unroll
        for (int j = 0; j < 8; j++)
#pragma unroll
            for (int e = 0; e < 4; e++) s[j][e] = 0.0f;
#pragma unroll
        for (int ks = 0; ks < 16; ks++) {
#pragma unroll
            for (int j = 0; j < 8; j++) {
                uint32_t bfr[2];
                const uint32_t* kp = Ks + (j*8 + g)*KV_STR + ks*8 + t;
                bfr[0] = kp[0];
                bfr[1] = kp[4];
                mma8(s[j], aQ[ks], bfr);
            }
        }

        const int row_g  = q0 + m0 + g;
        const int row_g8 = row_g + 8;
        const bool diag = (k0 + 63 > row_g);
#pragma unroll
        for (int j = 0; j < 8; j++) {
            int c0 = k0 + j*8 + 2*t;
            float y0 = __expf(s[j][0]*scl), y1 = __expf(s[j][1]*scl);
            float y2 = __expf(s[j][2]*scl), y3 = __expf(s[j][3]*scl);
            float p0 = __expf(y0), p1 = __expf(y1);
            float p2 = __expf(y2), p3 = __expf(y3);
            if (diag) {
                if (c0     > row_g ) p0 = 0.0f;
                if (c0 + 1 > row_g ) p1 = 0.0f;
                if (c0     > row_g8) p2 = 0.0f;
                if (c0 + 1 > row_g8) p3 = 0.0f;
            }
            uint32_t u0 = f2t(p0), u1 = f2t(p1), u2 = f2t(p2), u3 = f2t(p3);
            l0 += __uint_as_float(u0) + __uint_as_float(u1);
            l1 += __uint_as_float(u2) + __uint_as_float(u3);
            *(uint2*)(Ps + (m0 + g)*PS_STR + j*8 + 2*t)     = make_uint2(u0, u1);
            *(uint2*)(Ps + (m0 + g + 8)*PS_STR + j*8 + 2*t) = make_uint2(u2, u3);
        }
        __syncwarp();

#pragma unroll
        for (int ks = 0; ks < 8; ks++) {
            uint32_t aP[4];
            const uint32_t* pp = Ps + (m0 + g)*PS_STR + ks*8 + t;
            aP[0] = pp[0];
            aP[1] = pp[8*PS_STR];
            aP[2] = pp[4];
            aP[3] = pp[8*PS_STR + 4];
#pragma unroll
            for (int j = 0; j < 16; j++) {
                uint32_t bfr[2];
                const uint32_t* vp = Vs + (ks*8 + t)*KV_STR + j*8 + g;
                bfr[0] = vp[0];
                bfr[1] = vp[4*KV_STR];
                mma8(accO[j], aP, bfr);
            }
        }
        __syncthreads();
    }

    l0 += __shfl_xor_sync(0xffffffffu, l0, 1);
    l0 += __shfl_xor_sync(0xffffffffu, l0, 2);
    l1 += __shfl_xor_sync(0xffffffffu, l1, 1);
    l1 += __shfl_xor_sync(0xffffffffu, l1, 2);
    const float r0 = 1.0f / l0, r1 = 1.0f / l1;

    float* outp = out + ((long)b*SS + q0 + m0 + g)*HIDD + h*DHH;
#pragma unroll
    for (int j = 0; j < 16; j++) {
        int col = j*8 + 2*t;
        *(float2*)(outp + col)          = make_float2(accO[j][0]*r0, accO[j][1]*r0);
        *(float2*)(outp + 8*HIDD + col) = make_float2(accO[j][2]*r1, accO[j][3]*r1);
    }
}

// ---------------------------------------------------------------------------
extern "C" void kernel_launch(void* const* d_in, const int* in_sizes, int n_in,
                              void* d_out, int out_size)
{
    const float* queries = (const float*)d_in[0];
    const float* Wq = (const float*)d_in[1];
    const float* bq = (const float*)d_in[2];
    const float* Wk = (const float*)d_in[3];
    const float* bk = (const float*)d_in[4];
    const float* Wv = (const float*)d_in[5];
    const float* bv = (const float*)d_in[6];
    float* out = (float*)d_out;

    cudaFuncSetAttribute(qkv_mma_kernel, cudaFuncAttributeMaxDynamicSharedMemorySize, GSM_BYTES);
    cudaFuncSetAttribute(attn_kernel, cudaFuncAttributeMaxDynamicSharedMemorySize, ASM_BYTES);

    prep_a_kernel<<<8192, 256>>>(queries);
    prep_w_kernel<<<dim3(1024, 1, 3), 256>>>(Wq, Wk, Wv);
    qkv_mma_kernel<<<dim3(8, 64, 3), 128, GSM_BYTES>>>(bq, bk, bv);
    attn_kernel<<<dim3(8, 64), 256, ASM_BYTES>>>(out);
}

// round 8
// speedup vs baseline: 2.1787x; 1.2771x over previous
#include <cuda_runtime.h>
#include <cuda_fp16.h>
#include <cstdint>

#define BB 8
#define SS 1024
#define FEAT 1024
#define HIDD 1024
#define HH 8
#define DHH 128
#define MTOT (BB*SS)
#define W2R 512      // f16x2 words per token row (HIDD/2)

// fragment-permuted tf32 operands for the QKV GEMM (unchanged from R7)
__device__ uint32_t g_Ap[MTOT/16 * FEAT/8 * 32 * 4];
__device__ uint32_t g_Wp[3][HIDD/16 * FEAT/8 * 32 * 4];
// f16x2-packed Q/K/V: [token][dim-pair word]
__device__ uint32_t g_Qh[MTOT*W2R];
__device__ uint32_t g_Kh[MTOT*W2R];
__device__ uint32_t g_Vh[MTOT*W2R];
// V transposed into token-pair pairs: [bh][dim(128)][tokenpair(512)]
__device__ uint32_t g_Vt[BB*HH*DHH*512];

__device__ __forceinline__ uint32_t f2t(float x) {
    uint32_t u;
    asm("cvt.rna.tf32.f32 %0, %1;" : "=r"(u) : "f"(x));
    return u;
}
__device__ __forceinline__ uint32_t packh2(float lo, float hi) {
    __half2 h = __floats2half2_rn(lo, hi);
    return *(uint32_t*)&h;
}
__device__ __forceinline__ uint32_t smaddr(const void* p) {
    return (uint32_t)__cvta_generic_to_shared(p);
}

#define CP16(dst,src) asm volatile("cp.async.cg.shared.global [%0], [%1], 16;" :: "r"(dst), "l"(src))
#define CPCOMMIT()    asm volatile("cp.async.commit_group;")
#define CPWAIT(n)     asm volatile("cp.async.wait_group %0;" :: "n"(n))

__device__ __forceinline__ void mma8(float* d, const uint32_t* a, const uint32_t* b) {
    asm volatile(
        "mma.sync.aligned.m16n8k8.row.col.f32.tf32.tf32.f32 "
        "{%0,%1,%2,%3}, {%4,%5,%6,%7}, {%8,%9}, {%0,%1,%2,%3};"
        : "+f"(d[0]), "+f"(d[1]), "+f"(d[2]), "+f"(d[3])
        : "r"(a[0]), "r"(a[1]), "r"(a[2]), "r"(a[3]), "r"(b[0]), "r"(b[1]));
}
__device__ __forceinline__ void mma16(float* d, uint32_t a0, uint32_t a1,
                                      uint32_t a2, uint32_t a3,
                                      uint32_t b0, uint32_t b1) {
    asm volatile(
        "mma.sync.aligned.m16n8k16.row.col.f32.f16.f16.f32 "
        "{%0,%1,%2,%3}, {%4,%5,%6,%7}, {%8,%9}, {%0,%1,%2,%3};"
        : "+f"(d[0]), "+f"(d[1]), "+f"(d[2]), "+f"(d[3])
        : "r"(a0), "r"(a1), "r"(a2), "r"(a3), "r"(b0), "r"(b1));
}

// ---------------------------------------------------------------------------
// Prep A / Prep W (unchanged from R7)
// ---------------------------------------------------------------------------
__global__ __launch_bounds__(256)
void prep_a_kernel(const float* __restrict__ A)
{
    int idx = blockIdx.x*256 + threadIdx.x;
    int lane = idx & 31;
    int ks   = (idx >> 5) & 127;
    int mblk = idx >> 12;
    int g = lane >> 2, t = lane & 3;
    int row = 16*mblk + g, col = 8*ks + t;
    const float* p0 = A + (long)row*FEAT + col;
    const float* p1 = A + (long)(row + 8)*FEAT + col;
    uint4 o;
    o.x = f2t(p0[0]);
    o.y = f2t(p1[0]);
    o.z = f2t(p0[4]);
    o.w = f2t(p1[4]);
    *(uint4*)(g_Ap + (long)idx*4) = o;
}

__global__ __launch_bounds__(256)
void prep_w_kernel(const float* __restrict__ W0, const float* __restrict__ W1,
                   const float* __restrict__ W2)
{
    const float* W = (blockIdx.z == 0) ? W0 : (blockIdx.z == 1 ? W1 : W2);
    int idx = blockIdx.x*256 + threadIdx.x;
    int lane = idx & 31;
    int ks   = (idx >> 5) & 127;
    int jp   = idx >> 12;
    int g = lane >> 2, t = lane & 3;
    int kr = 8*ks + t;
    int n0 = 16*jp + g;
    uint4 o;
    o.x = f2t(W[(long)kr*HIDD + n0]);
    o.y = f2t(W[(long)(kr + 4)*HIDD + n0]);
    o.z = f2t(W[(long)kr*HIDD + n0 + 8]);
    o.w = f2t(W[(long)(kr + 4)*HIDD + n0 + 8]);
    *(uint4*)(g_Wp[blockIdx.z] + (long)idx*4) = o;
}

// ---------------------------------------------------------------------------
// Pass 1: QKV GEMM (R7 mainloop), epilogue writes f16x2 dim-pairs.
// ---------------------------------------------------------------------------
#define QSTG_W 8192
#define GSM_BYTES (2*QSTG_W*4)

__global__ __launch_bounds__(128)
void qkv_mma_kernel(const float* __restrict__ bq, const float* __restrict__ bk,
                    const float* __restrict__ bv)
{
    extern __shared__ uint32_t smg[];
    const int tid = threadIdx.x;
    const int w = tid >> 5, lane = tid & 31;
    const int g = lane >> 2, t = lane & 3;
    const int mw = (w >> 1) * 64, nw = (w & 1) * 64;
    const int row0 = blockIdx.y * 128, col0 = blockIdx.x * 128;
    const int mb0 = row0 >> 4, jp0 = col0 >> 4;

    const uint32_t* Wp = g_Wp[blockIdx.z];
    const float* bias  = (blockIdx.z == 0) ? bq  : (blockIdx.z == 1 ? bk  : bv);
    uint32_t* Og       = (blockIdx.z == 0) ? g_Qh : (blockIdx.z == 1 ? g_Kh : g_Vh);

    float acc[4][8][4];
#pragma unroll
    for (int i = 0; i < 4; i++)
#pragma unroll
        for (int j = 0; j < 8; j++)
#pragma unroll
            for (int e = 0; e < 4; e++) acc[i][j][e] = 0.0f;

    auto issue = [&](int it) {
        uint32_t base = smaddr(smg + (it & 1)*QSTG_W);
        int ks0 = it * 4;
#pragma unroll
        for (int i = 0; i < 8; i++) {
            int c = tid + i*128;
            int mloc = c >> 7, ksl = (c >> 5) & 3, lc = c & 31;
            CP16(base + c*16,
                 g_Ap + (((long)(mb0 + mloc)*128 + ks0 + ksl)*32 + lc)*4);
        }
        uint32_t baseB = base + 4096*4;
#pragma unroll
        for (int i = 0; i < 8; i++) {
            int c = tid + i*128;
            int jloc = c >> 7, ksl = (c >> 5) & 3, lc = c & 31;
            CP16(baseB + c*16,
                 Wp + (((long)(jp0 + jloc)*128 + ks0 + ksl)*32 + lc)*4);
        }
    };

    issue(0); CPCOMMIT();
    for (int it = 0; it < 32; ++it) {
        if (it + 1 < 32) issue(it + 1);
        CPCOMMIT();
        CPWAIT(1);
        __syncthreads();
        const uint32_t* As = smg + (it & 1)*QSTG_W;
        const uint32_t* Bs = As + 4096;
#pragma unroll
        for (int ks = 0; ks < 4; ks++) {
            uint32_t a[4][4], b[4][4];
#pragma unroll
            for (int i = 0; i < 4; i++) {
                int mloc = (mw >> 4) + i;
                *(uint4*)a[i] = *(const uint4*)(As + ((mloc*4 + ks)*32 + lane)*4);
            }
#pragma unroll
            for (int jp = 0; jp < 4; jp++) {
                int jloc = (nw >> 4) + jp;
                *(uint4*)b[jp] = *(const uint4*)(Bs + ((jloc*4 + ks)*32 + lane)*4);
            }
#pragma unroll
            for (int i = 0; i < 4; i++)
#pragma unroll
                for (int jp = 0; jp < 4; jp++) {
                    mma8(acc[i][2*jp],     a[i], &b[jp][0]);
                    mma8(acc[i][2*jp + 1], a[i], &b[jp][2]);
                }
        }
        __syncthreads();
    }

    // epilogue: + bias, pack f16x2 (dims 2t,2t+1 are lane-local), store
#pragma unroll
    for (int j = 0; j < 8; j++) {
        int col = col0 + nw + j*8 + 2*t;
        int colw = ((col0 + nw + j*8) >> 1) + t;
        float b0 = bias[col], b1 = bias[col + 1];
#pragma unroll
        for (int i = 0; i < 4; i++) {
            int row = row0 + mw + i*16 + g;
            Og[(long)row*W2R + colw]       = packh2(acc[i][j][0] + b0, acc[i][j][1] + b1);
            Og[(long)(row + 8)*W2R + colw] = packh2(acc[i][j][2] + b0, acc[i][j][3] + b1);
        }
    }
}

// ---------------------------------------------------------------------------
// V permute: g_Vh [token][dim-pairs] -> g_Vt [bh][dim][tokenpair] (f16x2 over
// adjacent tokens). Block = (tpg, bh): 64 tokens x 128 dims tile.
// ---------------------------------------------------------------------------
__global__ __launch_bounds__(256)
void v_permute_kernel()
{
    __shared__ uint32_t sv[64*65];
    const int tid = threadIdx.x;
    const int bh = blockIdx.y, b = bh >> 3, h = bh & 7;
    const int tok0 = blockIdx.x * 64, tp0 = blockIdx.x * 32;

#pragma unroll
    for (int i = 0; i < 16; i++) {
        int idx = tid + i*256;                 // 0..4095
        int r = idx >> 6, wd = idx & 63;
        sv[r*65 + wd] = g_Vh[((long)(b*SS + tok0 + r))*W2R + h*64 + wd];
    }
    __syncthreads();
#pragma unroll
    for (int i = 0; i < 16; i++) {
        int idx = tid + i*256;
        int dim = idx >> 5, tpl = idx & 31;
        uint32_t w0 = sv[(2*tpl)*65 + (dim >> 1)];
        uint32_t w1 = sv[(2*tpl + 1)*65 + (dim >> 1)];
        uint32_t o = (dim & 1) ? __byte_perm(w0, w1, 0x7632)
                               : __byte_perm(w0, w1, 0x5410);
        g_Vt[((long)bh*DHH + dim)*512 + tp0 + tpl] = o;
    }
}

// ---------------------------------------------------------------------------
// Pass 2: causal attention, f16 mma.m16n8k16, P register-resident.
// 256 threads (8 warps x 16 q-rows), q-tile 128, k-tile 64, double buffer.
// K smem [64 tok][68w] (f16x2 dim-pairs), Vt smem [128 dim][36w] (token-pairs).
// ---------------------------------------------------------------------------
#define KH_STR 68
#define VT_STR 36
#define KTILE_W (64*KH_STR)               // 4352 words
#define VTILE_W (128*VT_STR)              // 4608 words
#define STAGE_W (KTILE_W + VTILE_W)       // 8960 words
#define ASM_BYTES (2*STAGE_W*4)           // 71,680 B

__global__ __launch_bounds__(256)
void attn_kernel(float* __restrict__ out)
{
    extern __shared__ uint32_t sm[];

    const int tid = threadIdx.x;
    const int w = tid >> 5, lane = tid & 31;
    const int g = lane >> 2, t = lane & 3;
    const int m0 = w * 16;
    const int qt = 7 - blockIdx.x;
    const int q0 = qt * 128;
    const int bh = blockIdx.y, b = bh >> 3, h = bh & 7;
    const int nk = 2*qt + 2;

    const uint32_t* Qg = g_Qh + (long)b*SS*W2R + h*64;
    const uint32_t* Kg = g_Kh + (long)b*SS*W2R + h*64;
    const uint32_t* Vtg = g_Vt + (long)bh*DHH*512;

    // stage Q tile [128 tok x 64 words] into stage area
    {
        uint32_t base = smaddr(sm);
#pragma unroll
        for (int i = 0; i < 8; i++) {
            int c = tid + i*256;               // 0..2047
            int r = c >> 4, part = c & 15;
            CP16(base + (r*KH_STR + part*4)*4, Qg + (long)(q0 + r)*W2R + part*4);
        }
        CPCOMMIT(); CPWAIT(0);
    }
    __syncthreads();

    // A-fragments of Q: 8 kgroups x 4 regs (f16x2)
    uint32_t aQ[8][4];
#pragma unroll
    for (int K = 0; K < 8; K++) {
        aQ[K][0] = sm[(m0 + g)*KH_STR + 8*K + t];
        aQ[K][1] = sm[(m0 + g + 8)*KH_STR + 8*K + t];
        aQ[K][2] = sm[(m0 + g)*KH_STR + 8*K + t + 4];
        aQ[K][3] = sm[(m0 + g + 8)*KH_STR + 8*K + t + 4];
    }
    __syncthreads();

    float accO[16][4];
#pragma unroll
    for (int j = 0; j < 16; j++)
#pragma unroll
        for (int e = 0; e < 4; e++) accO[j][e] = 0.0f;
    float l0 = 0.0f, l1 = 0.0f;
    const float scl = 0.08838834764831843f;    // 1/sqrt(128)
    const float LN16 = 2.772588722239781f;     // p = exp(y)/16

    auto issue = [&](int kt) {
        uint32_t baseK = smaddr(sm + (kt & 1)*STAGE_W);
        uint32_t baseV = baseK + KTILE_W*4;
        int k0 = kt * 64;
#pragma unroll
        for (int i = 0; i < 4; i++) {
            int c = tid + i*256;               // 0..1023  K fill
            int r = c >> 4, part = c & 15;
            CP16(baseK + (r*KH_STR + part*4)*4, Kg + (long)(k0 + r)*W2R + part*4);
        }
#pragma unroll
        for (int i = 0; i < 4; i++) {
            int c = tid + i*256;               // 0..1023  V fill
            int dim = c >> 3, part = c & 7;
            CP16(baseV + (dim*VT_STR + part*4)*4,
                 Vtg + (long)dim*512 + kt*32 + part*4);
        }
    };

    issue(0); CPCOMMIT();
    for (int kt = 0; kt < nk; kt++) {
        if (kt + 1 < nk) issue(kt + 1);
        CPCOMMIT();
        CPWAIT(1);
        __syncthreads();
        const uint32_t* Ks = sm + (kt & 1)*STAGE_W;
        const uint32_t* Vs = Ks + KTILE_W;
        const int k0 = kt * 64;

        // S = Q K^T : 8 kgroups x 8 token-blocks, m16n8k16
        float s[8][4];
#pragma unroll
        for (int j = 0; j < 8; j++)
#pragma unroll
            for (int e = 0; e < 4; e++) s[j][e] = 0.0f;
#pragma unroll
        for (int K = 0; K < 8; K++) {
#pragma unroll
            for (int j = 0; j < 8; j++) {
                uint32_t b0 = Ks[(j*8 + g)*KH_STR + 8*K + t];
                uint32_t b1 = Ks[(j*8 + g)*KH_STR + 8*K + t + 4];
                mma16(s[j], aQ[K][0], aQ[K][1], aQ[K][2], aQ[K][3], b0, b1);
            }
        }

        // p = exp(exp(s/sqrt(d)) - ln16), causal mask near diagonal
        const int row_g  = q0 + m0 + g;
        const int row_g8 = row_g + 8;
        const bool diag = (k0 + 63 > row_g);
#pragma unroll
        for (int j = 0; j < 8; j++) {
            int c0 = k0 + j*8 + 2*t;
            float y0 = __expf(s[j][0]*scl), y1 = __expf(s[j][1]*scl);
            float y2 = __expf(s[j][2]*scl), y3 = __expf(s[j][3]*scl);
            float p0 = __expf(y0 - LN16), p1 = __expf(y1 - LN16);
            float p2 = __expf(y2 - LN16), p3 = __expf(y3 - LN16);
            if (diag) {
                if (c0     > row_g ) p0 = 0.0f;
                if (c0 + 1 > row_g ) p1 = 0.0f;
                if (c0     > row_g8) p2 = 0.0f;
                if (c0 + 1 > row_g8) p3 = 0.0f;
            }
            l0 += p0 + p1;
            l1 += p2 + p3;
            s[j][0] = p0; s[j][1] = p1; s[j][2] = p2; s[j][3] = p3;
        }

        // O += P V : P packs register->fragment (k16 layout matches producer)
#pragma unroll
        for (int J = 0; J < 4; J++) {
            uint32_t a0 = packh2(s[2*J][0],     s[2*J][1]);
            uint32_t a1 = packh2(s[2*J][2],     s[2*J][3]);
            uint32_t a2 = packh2(s[2*J + 1][0], s[2*J + 1][1]);
            uint32_t a3 = packh2(s[2*J + 1][2], s[2*J + 1][3]);
#pragma unroll
            for (int jb = 0; jb < 16; jb++) {
                uint32_t b0 = Vs[(jb*8 + g)*VT_STR + 8*J + t];
                uint32_t b1 = Vs[(jb*8 + g)*VT_STR + 8*J + t + 4];
                mma16(accO[jb], a0, a1, a2, a3, b0, b1);
            }
        }
        __syncthreads();
    }

    // row-sum reduce across the quad, normalize, store
    l0 += __shfl_xor_sync(0xffffffffu, l0, 1);
    l0 += __shfl_xor_sync(0xffffffffu, l0, 2);
    l1 += __shfl_xor_sync(0xffffffffu, l1, 1);
    l1 += __shfl_xor_sync(0xffffffffu, l1, 2);
    const float r0 = 1.0f / l0, r1 = 1.0f / l1;

    float* outp = out + ((long)b*SS + q0 + m0 + g)*HIDD + h*DHH;
#pragma unroll
    for (int j = 0; j < 16; j++) {
        int col = j*8 + 2*t;
        *(float2*)(outp + col)          = make_float2(accO[j][0]*r0, accO[j][1]*r0);
        *(float2*)(outp + 8*HIDD + col) = make_float2(accO[j][2]*r1, accO[j][3]*r1);
    }
}

// ---------------------------------------------------------------------------
extern "C" void kernel_launch(void* const* d_in, const int* in_sizes, int n_in,
                              void* d_out, int out_size)
{
    const float* queries = (const float*)d_in[0];
    const float* Wq = (const float*)d_in[1];
    const float* bq = (const float*)d_in[2];
    const float* Wk = (const float*)d_in[3];
    const float* bk = (const float*)d_in[4];
    const float* Wv = (const float*)d_in[5];
    const float* bv = (const float*)d_in[6];
    float* out = (float*)d_out;

    cudaFuncSetAttribute(qkv_mma_kernel, cudaFuncAttributeMaxDynamicSharedMemorySize, GSM_BYTES);
    cudaFuncSetAttribute(attn_kernel, cudaFuncAttributeMaxDynamicSharedMemorySize, ASM_BYTES);

    prep_a_kernel<<<8192, 256>>>(queries);
    prep_w_kernel<<<dim3(1024, 1, 3), 256>>>(Wq, Wk, Wv);
    qkv_mma_kernel<<<dim3(8, 64, 3), 128, GSM_BYTES>>>(bq, bk, bv);
    v_permute_kernel<<<dim3(16, 64), 256>>>();
    attn_kernel<<<dim3(8, 64), 256, ASM_BYTES>>>(out);
}

// round 9
// speedup vs baseline: 3.0396x; 1.3952x over previous
#include <cuda_runtime.h>
#include <cuda_fp16.h>
#include <cstdint>

#define BB 8
#define SS 1024
#define FEAT 1024
#define HIDD 1024
#define HH 8
#define DHH 128
#define MTOT (BB*SS)
#define W2R 512      // f16x2 words per token row (HIDD/2)

// f16-fragment-permuted operands for the QKV GEMM (m16n8k16 layout)
// Ap: [mblk(512)][kg(64)][lane(32)][4 f16x2]   (A-fragment of m16k16 block)
// Wp: [z][jp(64)][kg(64)][lane(32)][4 f16x2]   (B-fragments of two n8k16 blocks)
__device__ uint32_t g_Ap[MTOT/16 * FEAT/16 * 32 * 4];
__device__ uint32_t g_Wp[3][HIDD/16 * FEAT/16 * 32 * 4];
// f16x2-packed Q/K/V: [token][dim-pair word]
__device__ uint32_t g_Qh[MTOT*W2R];
__device__ uint32_t g_Kh[MTOT*W2R];
__device__ uint32_t g_Vh[MTOT*W2R];
// V transposed into token-pair pairs: [bh][dim(128)][tokenpair(512)]
__device__ uint32_t g_Vt[BB*HH*DHH*512];

__device__ __forceinline__ uint32_t packh2(float lo, float hi) {
    __half2 h = __floats2half2_rn(lo, hi);
    return *(uint32_t*)&h;
}
__device__ __forceinline__ uint32_t smaddr(const void* p) {
    return (uint32_t)__cvta_generic_to_shared(p);
}

#define CP16(dst,src) asm volatile("cp.async.cg.shared.global [%0], [%1], 16;" :: "r"(dst), "l"(src))
#define CPCOMMIT()    asm volatile("cp.async.commit_group;")
#define CPWAIT(n)     asm volatile("cp.async.wait_group %0;" :: "n"(n))

__device__ __forceinline__ void mma16(float* d, uint32_t a0, uint32_t a1,
                                      uint32_t a2, uint32_t a3,
                                      uint32_t b0, uint32_t b1) {
    asm volatile(
        "mma.sync.aligned.m16n8k16.row.col.f32.f16.f16.f32 "
        "{%0,%1,%2,%3}, {%4,%5,%6,%7}, {%8,%9}, {%0,%1,%2,%3};"
        : "+f"(d[0]), "+f"(d[1]), "+f"(d[2]), "+f"(d[3])
        : "r"(a0), "r"(a1), "r"(a2), "r"(a3), "r"(b0), "r"(b1));
}

// ---------------------------------------------------------------------------
// Prep A: queries -> f16x2 A-fragments (m16n8k16), fragment-permuted order.
// One thread per (mblk, kg, lane) 16B chunk.
// ---------------------------------------------------------------------------
__global__ __launch_bounds__(256)
void prep_a_kernel(const float* __restrict__ A)
{
    int idx = blockIdx.x*256 + threadIdx.x;      // 0 .. 512*64*32-1
    int lane = idx & 31;
    int kg   = (idx >> 5) & 63;
    int mblk = idx >> 11;
    int g = lane >> 2, t = lane & 3;
    int row = 16*mblk + g, col = 16*kg + 2*t;
    const float* p0 = A + (long)row*FEAT + col;
    const float* p1 = A + (long)(row + 8)*FEAT + col;
    uint4 o;
    o.x = packh2(p0[0], p0[1]);
    o.y = packh2(p1[0], p1[1]);
    o.z = packh2(p0[8], p0[9]);
    o.w = packh2(p1[8], p1[9]);
    *(uint4*)(g_Ap + (long)idx*4) = o;
}

// ---------------------------------------------------------------------------
// Prep W: weights -> f16x2 B-fragments of two n8k16 blocks packed per lane.
// ---------------------------------------------------------------------------
__global__ __launch_bounds__(256)
void prep_w_kernel(const float* __restrict__ W0, const float* __restrict__ W1,
                   const float* __restrict__ W2)
{
    const float* W = (blockIdx.z == 0) ? W0 : (blockIdx.z == 1 ? W1 : W2);
    int idx = blockIdx.x*256 + threadIdx.x;      // 0 .. 64*64*32-1
    int lane = idx & 31;
    int kg   = (idx >> 5) & 63;
    int jp   = idx >> 11;
    int g = lane >> 2, t = lane & 3;
    int kr = 16*kg + 2*t;
    int n0 = 16*jp + g;
    uint4 o;
    o.x = packh2(W[(long)kr*HIDD + n0],       W[(long)(kr+1)*HIDD + n0]);       // j0 b0
    o.y = packh2(W[(long)(kr+8)*HIDD + n0],   W[(long)(kr+9)*HIDD + n0]);       // j0 b1
    o.z = packh2(W[(long)kr*HIDD + n0 + 8],   W[(long)(kr+1)*HIDD + n0 + 8]);   // j1 b0
    o.w = packh2(W[(long)(kr+8)*HIDD + n0+8], W[(long)(kr+9)*HIDD + n0 + 8]);   // j1 b1
    *(uint4*)(g_Wp[blockIdx.z] + (long)idx*4) = o;
}

// ---------------------------------------------------------------------------
// Pass 1: QKV projection GEMM, f16 mma.m16n8k16, fragment-permuted smem:
// every fragment load is one conflict-free LDS.128.
// 128 threads (4 warps, 64x64), block tile 128x128, K-step 32 (2 kgroups),
// double buffer. Smem per stage: A 8KB + B 8KB.
// ---------------------------------------------------------------------------
#define QSTG_W 4096                     // words per stage (A 2048 + B 2048)
#define GSM_BYTES (2*QSTG_W*4)          // 32768

__global__ __launch_bounds__(128)
void qkv_mma_kernel(const float* __restrict__ bq, const float* __restrict__ bk,
                    const float* __restrict__ bv)
{
    extern __shared__ uint32_t smg[];
    const int tid = threadIdx.x;
    const int w = tid >> 5, lane = tid & 31;
    const int g = lane >> 2, t = lane & 3;
    const int mw = (w >> 1) * 64, nw = (w & 1) * 64;   // warp tile origin
    const int row0 = blockIdx.y * 128, col0 = blockIdx.x * 128;
    const int mb0 = row0 >> 4, jp0 = col0 >> 4;        // global block indices

    const uint32_t* Wp = g_Wp[blockIdx.z];
    const float* bias  = (blockIdx.z == 0) ? bq  : (blockIdx.z == 1 ? bk  : bv);
    uint32_t* Og       = (blockIdx.z == 0) ? g_Qh : (blockIdx.z == 1 ? g_Kh : g_Vh);

    float acc[4][8][4];
#pragma unroll
    for (int i = 0; i < 4; i++)
#pragma unroll
        for (int j = 0; j < 8; j++)
#pragma unroll
            for (int e = 0; e < 4; e++) acc[i][j][e] = 0.0f;

    // stage layout: A chunks c=0..511: mloc=c>>6, kgl=(c>>5)&1, lane=c&31
    //               B chunks likewise after 2048 words.
    auto issue = [&](int it) {
        uint32_t base = smaddr(smg + (it & 1)*QSTG_W);
        int kg0 = it * 2;                       // global kgroup base (K-step 32)
#pragma unroll
        for (int i = 0; i < 4; i++) {
            int c = tid + i*128;                // 0..511
            int mloc = c >> 6, kgl = (c >> 5) & 1, lc = c & 31;
            CP16(base + c*16,
                 g_Ap + (((long)(mb0 + mloc)*64 + kg0 + kgl)*32 + lc)*4);
        }
        uint32_t baseB = base + 2048*4;
#pragma unroll
        for (int i = 0; i < 4; i++) {
            int c = tid + i*128;
            int jloc = c >> 6, kgl = (c >> 5) & 1, lc = c & 31;
            CP16(baseB + c*16,
                 Wp + (((long)(jp0 + jloc)*64 + kg0 + kgl)*32 + lc)*4);
        }
    };

    issue(0); CPCOMMIT();
    for (int it = 0; it < 32; ++it) {
        if (it + 1 < 32) issue(it + 1);
        CPCOMMIT();
        CPWAIT(1);
        __syncthreads();
        const uint32_t* As = smg + (it & 1)*QSTG_W;
        const uint32_t* Bs = As + 2048;
#pragma unroll
        for (int kgl = 0; kgl < 2; kgl++) {
            uint32_t a[4][4], b[4][4];
#pragma unroll
            for (int i = 0; i < 4; i++) {
                int mloc = (mw >> 4) + i;
                *(uint4*)a[i] = *(const uint4*)(As + ((mloc*2 + kgl)*32 + lane)*4);
            }
#pragma unroll
            for (int jp = 0; jp < 4; jp++) {
                int jloc = (nw >> 4) + jp;
                *(uint4*)b[jp] = *(const uint4*)(Bs + ((jloc*2 + kgl)*32 + lane)*4);
            }
#pragma unroll
            for (int i = 0; i < 4; i++)
#pragma unroll
                for (int jp = 0; jp < 4; jp++) {
                    mma16(acc[i][2*jp],     a[i][0], a[i][1], a[i][2], a[i][3],
                          b[jp][0], b[jp][1]);
                    mma16(acc[i][2*jp + 1], a[i][0], a[i][1], a[i][2], a[i][3],
                          b[jp][2], b[jp][3]);
                }
        }
        __syncthreads();
    }

    // epilogue: + bias, pack f16x2 (dims 2t,2t+1 are lane-local), store
#pragma unroll
    for (int j = 0; j < 8; j++) {
        int col = col0 + nw + j*8 + 2*t;
        int colw = ((col0 + nw + j*8) >> 1) + t;
        float b0 = bias[col], b1 = bias[col + 1];
#pragma unroll
        for (int i = 0; i < 4; i++) {
            int row = row0 + mw + i*16 + g;
            Og[(long)row*W2R + colw]       = packh2(acc[i][j][0] + b0, acc[i][j][1] + b1);
            Og[(long)(row + 8)*W2R + colw] = packh2(acc[i][j][2] + b0, acc[i][j][3] + b1);
        }
    }
}

// ---------------------------------------------------------------------------
// V permute (unchanged from R8)
// ---------------------------------------------------------------------------
__global__ __launch_bounds__(256)
void v_permute_kernel()
{
    __shared__ uint32_t sv[64*65];
    const int tid = threadIdx.x;
    const int bh = blockIdx.y, b = bh >> 3, h = bh & 7;
    const int tok0 = blockIdx.x * 64, tp0 = blockIdx.x * 32;

#pragma unroll
    for (int i = 0; i < 16; i++) {
        int idx = tid + i*256;
        int r = idx >> 6, wd = idx & 63;
        sv[r*65 + wd] = g_Vh[((long)(b*SS + tok0 + r))*W2R + h*64 + wd];
    }
    __syncthreads();
#pragma unroll
    for (int i = 0; i < 16; i++) {
        int idx = tid + i*256;
        int dim = idx >> 5, tpl = idx & 31;
        uint32_t w0 = sv[(2*tpl)*65 + (dim >> 1)];
        uint32_t w1 = sv[(2*tpl + 1)*65 + (dim >> 1)];
        uint32_t o = (dim & 1) ? __byte_perm(w0, w1, 0x7632)
                               : __byte_perm(w0, w1, 0x5410);
        g_Vt[((long)bh*DHH + dim)*512 + tp0 + tpl] = o;
    }
}

// ---------------------------------------------------------------------------
// Pass 2: causal attention (unchanged from R8, measured ~125us).
// ---------------------------------------------------------------------------
#define KH_STR 68
#define VT_STR 36
#define KTILE_W (64*KH_STR)
#define VTILE_W (128*VT_STR)
#define STAGE_W (KTILE_W + VTILE_W)
#define ASM_BYTES (2*STAGE_W*4)

__global__ __launch_bounds__(256)
void attn_kernel(float* __restrict__ out)
{
    extern __shared__ uint32_t sm[];

    const int tid = threadIdx.x;
    const int w = tid >> 5, lane = tid & 31;
    const int g = lane >> 2, t = lane & 3;
    const int m0 = w * 16;
    const int qt = 7 - blockIdx.x;
    const int q0 = qt * 128;
    const int bh = blockIdx.y, b = bh >> 3, h = bh & 7;
    const int nk = 2*qt + 2;

    const uint32_t* Qg = g_Qh + (long)b*SS*W2R + h*64;
    const uint32_t* Kg = g_Kh + (long)b*SS*W2R + h*64;
    const uint32_t* Vtg = g_Vt + (long)bh*DHH*512;

    {
        uint32_t base = smaddr(sm);
#pragma unroll
        for (int i = 0; i < 8; i++) {
            int c = tid + i*256;
            int r = c >> 4, part = c & 15;
            CP16(base + (r*KH_STR + part*4)*4, Qg + (long)(q0 + r)*W2R + part*4);
        }
        CPCOMMIT(); CPWAIT(0);
    }
    __syncthreads();

    uint32_t aQ[8][4];
#pragma unroll
    for (int K = 0; K < 8; K++) {
        aQ[K][0] = sm[(m0 + g)*KH_STR + 8*K + t];
        aQ[K][1] = sm[(m0 + g + 8)*KH_STR + 8*K + t];
        aQ[K][2] = sm[(m0 + g)*KH_STR + 8*K + t + 4];
        aQ[K][3] = sm[(m0 + g + 8)*KH_STR + 8*K + t + 4];
    }
    __syncthreads();

    float accO[16][4];
#pragma unroll
    for (int j = 0; j < 16; j++)
#pragma unroll
        for (int e = 0; e < 4; e++) accO[j][e] = 0.0f;
    float l0 = 0.0f, l1 = 0.0f;
    const float scl = 0.08838834764831843f;
    const float LN16 = 2.772588722239781f;

    auto issue = [&](int kt) {
        uint32_t baseK = smaddr(sm + (kt & 1)*STAGE_W);
        uint32_t baseV = baseK + KTILE_W*4;
        int k0 = kt * 64;
#pragma unroll
        for (int i = 0; i < 4; i++) {
            int c = tid + i*256;
            int r = c >> 4, part = c & 15;
            CP16(baseK + (r*KH_STR + part*4)*4, Kg + (long)(k0 + r)*W2R + part*4);
        }
#pragma unroll
        for (int i = 0; i < 4; i++) {
            int c = tid + i*256;
            int dim = c >> 3, part = c & 7;
            CP16(baseV + (dim*VT_STR + part*4)*4,
                 Vtg + (long)dim*512 + kt*32 + part*4);
        }
    };

    issue(0); CPCOMMIT();
    for (int kt = 0; kt < nk; kt++) {
        if (kt + 1 < nk) issue(kt + 1);
        CPCOMMIT();
        CPWAIT(1);
        __syncthreads();
        const uint32_t* Ks = sm + (kt & 1)*STAGE_W;
        const uint32_t* Vs = Ks + KTILE_W;
        const int k0 = kt * 64;

        float s[8][4];
#pragma unroll
        for (int j = 0; j < 8; j++)
#pragma unroll
            for (int e = 0; e < 4; e++) s[j][e] = 0.0f;
#pragma unroll
        for (int K = 0; K < 8; K++) {
#pragma unroll
            for (int j = 0; j < 8; j++) {
                uint32_t b0 = Ks[(j*8 + g)*KH_STR + 8*K + t];
                uint32_t b1 = Ks[(j*8 + g)*KH_STR + 8*K + t + 4];
                mma16(s[j], aQ[K][0], aQ[K][1], aQ[K][2], aQ[K][3], b0, b1);
            }
        }

        const int row_g  = q0 + m0 + g;
        const int row_g8 = row_g + 8;
        const bool diag = (k0 + 63 > row_g);
#pragma unroll
        for (int j = 0; j < 8; j++) {
            int c0 = k0 + j*8 + 2*t;
            float y0 = __expf(s[j][0]*scl), y1 = __expf(s[j][1]*scl);
            float y2 = __expf(s[j][2]*scl), y3 = __expf(s[j][3]*scl);
            float p0 = __expf(y0 - LN16), p1 = __expf(y1 - LN16);
            float p2 = __expf(y2 - LN16), p3 = __expf(y3 - LN16);
            if (diag) {
                if (c0     > row_g ) p0 = 0.0f;
                if (c0 + 1 > row_g ) p1 = 0.0f;
                if (c0     > row_g8) p2 = 0.0f;
                if (c0 + 1 > row_g8) p3 = 0.0f;
            }
            l0 += p0 + p1;
            l1 += p2 + p3;
            s[j][0] = p0; s[j][1] = p1; s[j][2] = p2; s[j][3] = p3;
        }

#pragma unroll
        for (int J = 0; J < 4; J++) {
            uint32_t a0 = packh2(s[2*J][0],     s[2*J][1]);
            uint32_t a1 = packh2(s[2*J][2],     s[2*J][3]);
            uint32_t a2 = packh2(s[2*J + 1][0], s[2*J + 1][1]);
            uint32_t a3 = packh2(s[2*J + 1][2], s[2*J + 1][3]);
#pragma unroll
            for (int jb = 0; jb < 16; jb++) {
                uint32_t b0 = Vs[(jb*8 + g)*VT_STR + 8*J + t];
                uint32_t b1 = Vs[(jb*8 + g)*VT_STR + 8*J + t + 4];
                mma16(accO[jb], a0, a1, a2, a3, b0, b1);
            }
        }
        __syncthreads();
    }

    l0 += __shfl_xor_sync(0xffffffffu, l0, 1);
    l0 += __shfl_xor_sync(0xffffffffu, l0, 2);
    l1 += __shfl_xor_sync(0xffffffffu, l1, 1);
    l1 += __shfl_xor_sync(0xffffffffu, l1, 2);
    const float r0 = 1.0f / l0, r1 = 1.0f / l1;

    float* outp = out + ((long)b*SS + q0 + m0 + g)*HIDD + h*DHH;
#pragma unroll
    for (int j = 0; j < 16; j++) {
        int col = j*8 + 2*t;
        *(float2*)(outp + col)          = make_float2(accO[j][0]*r0, accO[j][1]*r0);
        *(float2*)(outp + 8*HIDD + col) = make_float2(accO[j][2]*r1, accO[j][3]*r1);
    }
}

// ---------------------------------------------------------------------------
extern "C" void kernel_launch(void* const* d_in, const int* in_sizes, int n_in,
                              void* d_out, int out_size)
{
    const float* queries = (const float*)d_in[0];
    const float* Wq = (const float*)d_in[1];
    const float* bq = (const float*)d_in[2];
    const float* Wk = (const float*)d_in[3];
    const float* bk = (const float*)d_in[4];
    const float* Wv = (const float*)d_in[5];
    const float* bv = (const float*)d_in[6];
    float* out = (float*)d_out;

    cudaFuncSetAttribute(qkv_mma_kernel, cudaFuncAttributeMaxDynamicSharedMemorySize, GSM_BYTES);
    cudaFuncSetAttribute(attn_kernel, cudaFuncAttributeMaxDynamicSharedMemorySize, ASM_BYTES);

    prep_a_kernel<<<4096, 256>>>(queries);
    prep_w_kernel<<<dim3(512, 1, 3), 256>>>(Wq, Wk, Wv);
    qkv_mma_kernel<<<dim3(8, 64, 3), 128, GSM_BYTES>>>(bq, bk, bv);
    v_permute_kernel<<<dim3(16, 64), 256>>>();
    attn_kernel<<<dim3(8, 64), 256, ASM_BYTES>>>(out);
}

// round 10
// speedup vs baseline: 3.1853x; 1.0479x over previous
#include <cuda_runtime.h>
#include <cuda_fp16.h>
#include <cstdint>

#define BB 8
#define SS 1024
#define FEAT 1024
#define HIDD 1024
#define HH 8
#define DHH 128
#define MTOT (BB*SS)
#define W2R 512      // f16x2 words per token row (HIDD/2)

// f16-fragment-permuted operands for the QKV GEMM (m16n8k16 layout)
__device__ uint32_t g_Ap[MTOT/16 * FEAT/16 * 32 * 4];
__device__ uint32_t g_Wp[3][HIDD/16 * FEAT/16 * 32 * 4];
// f16x2-packed Q/K/V: [token][dim-pair word]
__device__ uint32_t g_Qh[MTOT*W2R];
__device__ uint32_t g_Kh[MTOT*W2R];
__device__ uint32_t g_Vh[MTOT*W2R];
// V transposed into token-pair pairs: [bh][dim(128)][tokenpair(512)]
__device__ uint32_t g_Vt[BB*HH*DHH*512];

__device__ __forceinline__ uint32_t packh2(float lo, float hi) {
    __half2 h = __floats2half2_rn(lo, hi);
    return *(uint32_t*)&h;
}
__device__ __forceinline__ uint32_t smaddr(const void* p) {
    return (uint32_t)__cvta_generic_to_shared(p);
}

#define CP16(dst,src) asm volatile("cp.async.cg.shared.global [%0], [%1], 16;" :: "r"(dst), "l"(src))
#define CPCOMMIT()    asm volatile("cp.async.commit_group;")
#define CPWAIT(n)     asm volatile("cp.async.wait_group %0;" :: "n"(n))

__device__ __forceinline__ void mma16(float* d, uint32_t a0, uint32_t a1,
                                      uint32_t a2, uint32_t a3,
                                      uint32_t b0, uint32_t b1) {
    asm volatile(
        "mma.sync.aligned.m16n8k16.row.col.f32.f16.f16.f32 "
        "{%0,%1,%2,%3}, {%4,%5,%6,%7}, {%8,%9}, {%0,%1,%2,%3};"
        : "+f"(d[0]), "+f"(d[1]), "+f"(d[2]), "+f"(d[3])
        : "r"(a0), "r"(a1), "r"(a2), "r"(a3), "r"(b0), "r"(b1));
}

// ---------------------------------------------------------------------------
// Prep A / Prep W (unchanged from R9)
// ---------------------------------------------------------------------------
__global__ __launch_bounds__(256)
void prep_a_kernel(const float* __restrict__ A)
{
    int idx = blockIdx.x*256 + threadIdx.x;
    int lane = idx & 31;
    int kg   = (idx >> 5) & 63;
    int mblk = idx >> 11;
    int g = lane >> 2, t = lane & 3;
    int row = 16*mblk + g, col = 16*kg + 2*t;
    const float* p0 = A + (long)row*FEAT + col;
    const float* p1 = A + (long)(row + 8)*FEAT + col;
    uint4 o;
    o.x = packh2(p0[0], p0[1]);
    o.y = packh2(p1[0], p1[1]);
    o.z = packh2(p0[8], p0[9]);
    o.w = packh2(p1[8], p1[9]);
    *(uint4*)(g_Ap + (long)idx*4) = o;
}

__global__ __launch_bounds__(256)
void prep_w_kernel(const float* __restrict__ W0, const float* __restrict__ W1,
                   const float* __restrict__ W2)
{
    const float* W = (blockIdx.z == 0) ? W0 : (blockIdx.z == 1 ? W1 : W2);
    int idx = blockIdx.x*256 + threadIdx.x;
    int lane = idx & 31;
    int kg   = (idx >> 5) & 63;
    int jp   = idx >> 11;
    int g = lane >> 2, t = lane & 3;
    int kr = 16*kg + 2*t;
    int n0 = 16*jp + g;
    uint4 o;
    o.x = packh2(W[(long)kr*HIDD + n0],       W[(long)(kr+1)*HIDD + n0]);
    o.y = packh2(W[(long)(kr+8)*HIDD + n0],   W[(long)(kr+9)*HIDD + n0]);
    o.z = packh2(W[(long)kr*HIDD + n0 + 8],   W[(long)(kr+1)*HIDD + n0 + 8]);
    o.w = packh2(W[(long)(kr+8)*HIDD + n0+8], W[(long)(kr+9)*HIDD + n0 + 8]);
    *(uint4*)(g_Wp[blockIdx.z] + (long)idx*4) = o;
}

// ---------------------------------------------------------------------------
// Pass 1: QKV projection GEMM, f16 mma.m16n8k16 (unchanged from R9).
// ---------------------------------------------------------------------------
#define QSTG_W 4096
#define GSM_BYTES (2*QSTG_W*4)

__global__ __launch_bounds__(128)
void qkv_mma_kernel(const float* __restrict__ bq, const float* __restrict__ bk,
                    const float* __restrict__ bv)
{
    extern __shared__ uint32_t smg[];
    const int tid = threadIdx.x;
    const int w = tid >> 5, lane = tid & 31;
    const int g = lane >> 2, t = lane & 3;
    const int mw = (w >> 1) * 64, nw = (w & 1) * 64;
    const int row0 = blockIdx.y * 128, col0 = blockIdx.x * 128;
    const int mb0 = row0 >> 4, jp0 = col0 >> 4;

    const uint32_t* Wp = g_Wp[blockIdx.z];
    const float* bias  = (blockIdx.z == 0) ? bq  : (blockIdx.z == 1 ? bk  : bv);
    uint32_t* Og       = (blockIdx.z == 0) ? g_Qh : (blockIdx.z == 1 ? g_Kh : g_Vh);

    float acc[4][8][4];
#pragma unroll
    for (int i = 0; i < 4; i++)
#pragma unroll
        for (int j = 0; j < 8; j++)
#pragma unroll
            for (int e = 0; e < 4; e++) acc[i][j][e] = 0.0f;

    auto issue = [&](int it) {
        uint32_t base = smaddr(smg + (it & 1)*QSTG_W);
        int kg0 = it * 2;
#pragma unroll
        for (int i = 0; i < 4; i++) {
            int c = tid + i*128;
            int mloc = c >> 6, kgl = (c >> 5) & 1, lc = c & 31;
            CP16(base + c*16,
                 g_Ap + (((long)(mb0 + mloc)*64 + kg0 + kgl)*32 + lc)*4);
        }
        uint32_t baseB = base + 2048*4;
#pragma unroll
        for (int i = 0; i < 4; i++) {
            int c = tid + i*128;
            int jloc = c >> 6, kgl = (c >> 5) & 1, lc = c & 31;
            CP16(baseB + c*16,
                 Wp + (((long)(jp0 + jloc)*64 + kg0 + kgl)*32 + lc)*4);
        }
    };

    issue(0); CPCOMMIT();
    for (int it = 0; it < 32; ++it) {
        if (it + 1 < 32) issue(it + 1);
        CPCOMMIT();
        CPWAIT(1);
        __syncthreads();
        const uint32_t* As = smg + (it & 1)*QSTG_W;
        const uint32_t* Bs = As + 2048;
#pragma unroll
        for (int kgl = 0; kgl < 2; kgl++) {
            uint32_t a[4][4], b[4][4];
#pragma unroll
            for (int i = 0; i < 4; i++) {
                int mloc = (mw >> 4) + i;
                *(uint4*)a[i] = *(const uint4*)(As + ((mloc*2 + kgl)*32 + lane)*4);
            }
#pragma unroll
            for (int jp = 0; jp < 4; jp++) {
                int jloc = (nw >> 4) + jp;
                *(uint4*)b[jp] = *(const uint4*)(Bs + ((jloc*2 + kgl)*32 + lane)*4);
            }
#pragma unroll
            for (int i = 0; i < 4; i++)
#pragma unroll
                for (int jp = 0; jp < 4; jp++) {
                    mma16(acc[i][2*jp],     a[i][0], a[i][1], a[i][2], a[i][3],
                          b[jp][0], b[jp][1]);
                    mma16(acc[i][2*jp + 1], a[i][0], a[i][1], a[i][2], a[i][3],
                          b[jp][2], b[jp][3]);
                }
        }
        __syncthreads();
    }

#pragma unroll
    for (int j = 0; j < 8; j++) {
        int col = col0 + nw + j*8 + 2*t;
        int colw = ((col0 + nw + j*8) >> 1) + t;
        float b0 = bias[col], b1 = bias[col + 1];
#pragma unroll
        for (int i = 0; i < 4; i++) {
            int row = row0 + mw + i*16 + g;
            Og[(long)row*W2R + colw]       = packh2(acc[i][j][0] + b0, acc[i][j][1] + b1);
            Og[(long)(row + 8)*W2R + colw] = packh2(acc[i][j][2] + b0, acc[i][j][3] + b1);
        }
    }
}

// ---------------------------------------------------------------------------
// V permute (unchanged from R8)
// ---------------------------------------------------------------------------
__global__ __launch_bounds__(256)
void v_permute_kernel()
{
    __shared__ uint32_t sv[64*65];
    const int tid = threadIdx.x;
    const int bh = blockIdx.y, b = bh >> 3, h = bh & 7;
    const int tok0 = blockIdx.x * 64, tp0 = blockIdx.x * 32;

#pragma unroll
    for (int i = 0; i < 16; i++) {
        int idx = tid + i*256;
        int r = idx >> 6, wd = idx & 63;
        sv[r*65 + wd] = g_Vh[((long)(b*SS + tok0 + r))*W2R + h*64 + wd];
    }
    __syncthreads();
#pragma unroll
    for (int i = 0; i < 16; i++) {
        int idx = tid + i*256;
        int dim = idx >> 5, tpl = idx & 31;
        uint32_t w0 = sv[(2*tpl)*65 + (dim >> 1)];
        uint32_t w1 = sv[(2*tpl + 1)*65 + (dim >> 1)];
        uint32_t o = (dim & 1) ? __byte_perm(w0, w1, 0x7632)
                               : __byte_perm(w0, w1, 0x5410);
        g_Vt[((long)bh*DHH + dim)*512 + tp0 + tpl] = o;
    }
}

// ---------------------------------------------------------------------------
// Pass 2: causal attention, f16 mma, register-resident P.
// NOW: 128 threads (4 warps), q-tile 64, 2 CTAs/SM (regs 224*128*2 = 57K).
// Same per-warp tiling as R9 (m16 S-rows, n64 S-cols, n128 PV).
// ---------------------------------------------------------------------------
#define KH_STR 68
#define VT_STR 36
#define KTILE_W (64*KH_STR)
#define VTILE_W (128*VT_STR)
#define STAGE_W (KTILE_W + VTILE_W)
#define ASM_BYTES (2*STAGE_W*4)           // 71,680 B per CTA

__global__ __launch_bounds__(128, 2)
void attn_kernel(float* __restrict__ out)
{
    extern __shared__ uint32_t sm[];

    const int tid = threadIdx.x;
    const int w = tid >> 5, lane = tid & 31;
    const int g = lane >> 2, t = lane & 3;
    const int m0 = w * 16;
    const int qt = 15 - blockIdx.x;           // biggest blocks first
    const int q0 = qt * 64;
    const int bh = blockIdx.y, b = bh >> 3, h = bh & 7;
    const int nk = qt + 1;

    const uint32_t* Qg = g_Qh + (long)b*SS*W2R + h*64;
    const uint32_t* Kg = g_Kh + (long)b*SS*W2R + h*64;
    const uint32_t* Vtg = g_Vt + (long)bh*DHH*512;

    // stage Q tile [64 tok x 64 words]
    {
        uint32_t base = smaddr(sm);
#pragma unroll
        for (int i = 0; i < 8; i++) {
            int c = tid + i*128;               // 0..1023
            int r = c >> 4, part = c & 15;
            CP16(base + (r*KH_STR + part*4)*4, Qg + (long)(q0 + r)*W2R + part*4);
        }
        CPCOMMIT(); CPWAIT(0);
    }
    __syncthreads();

    uint32_t aQ[8][4];
#pragma unroll
    for (int K = 0; K < 8; K++) {
        aQ[K][0] = sm[(m0 + g)*KH_STR + 8*K + t];
        aQ[K][1] = sm[(m0 + g + 8)*KH_STR + 8*K + t];
        aQ[K][2] = sm[(m0 + g)*KH_STR + 8*K + t + 4];
        aQ[K][3] = sm[(m0 + g + 8)*KH_STR + 8*K + t + 4];
    }
    __syncthreads();

    float accO[16][4];
#pragma unroll
    for (int j = 0; j < 16; j++)
#pragma unroll
        for (int e = 0; e < 4; e++) accO[j][e] = 0.0f;
    float l0 = 0.0f, l1 = 0.0f;
    const float scl = 0.08838834764831843f;
    const float LN16 = 2.772588722239781f;

    auto issue = [&](int kt) {
        uint32_t baseK = smaddr(sm + (kt & 1)*STAGE_W);
        uint32_t baseV = baseK + KTILE_W*4;
        int k0 = kt * 64;
#pragma unroll
        for (int i = 0; i < 8; i++) {
            int c = tid + i*128;               // 0..1023  K fill
            int r = c >> 4, part = c & 15;
            CP16(baseK + (r*KH_STR + part*4)*4, Kg + (long)(k0 + r)*W2R + part*4);
        }
#pragma unroll
        for (int i = 0; i < 8; i++) {
            int c = tid + i*128;               // 0..1023  V fill
            int dim = c >> 3, part = c & 7;
            CP16(baseV + (dim*VT_STR + part*4)*4,
                 Vtg + (long)dim*512 + kt*32 + part*4);
        }
    };

    issue(0); CPCOMMIT();
    for (int kt = 0; kt < nk; kt++) {
        if (kt + 1 < nk) issue(kt + 1);
        CPCOMMIT();
        CPWAIT(1);
        __syncthreads();
        const uint32_t* Ks = sm + (kt & 1)*STAGE_W;
        const uint32_t* Vs = Ks + KTILE_W;
        const int k0 = kt * 64;

        float s[8][4];
#pragma unroll
        for (int j = 0; j < 8; j++)
#pragma unroll
            for (int e = 0; e < 4; e++) s[j][e] = 0.0f;
#pragma unroll
        for (int K = 0; K < 8; K++) {
#pragma unroll
            for (int j = 0; j < 8; j++) {
                uint32_t b0 = Ks[(j*8 + g)*KH_STR + 8*K + t];
                uint32_t b1 = Ks[(j*8 + g)*KH_STR + 8*K + t + 4];
                mma16(s[j], aQ[K][0], aQ[K][1], aQ[K][2], aQ[K][3], b0, b1);
            }
        }

        const int row_g  = q0 + m0 + g;
        const int row_g8 = row_g + 8;
        const bool diag = (k0 + 63 > row_g);
#pragma unroll
        for (int j = 0; j < 8; j++) {
            int c0 = k0 + j*8 + 2*t;
            float y0 = __expf(s[j][0]*scl), y1 = __expf(s[j][1]*scl);
            float y2 = __expf(s[j][2]*scl), y3 = __expf(s[j][3]*scl);
            float p0 = __expf(y0 - LN16), p1 = __expf(y1 - LN16);
            float p2 = __expf(y2 - LN16), p3 = __expf(y3 - LN16);
            if (diag) {
                if (c0     > row_g ) p0 = 0.0f;
                if (c0 + 1 > row_g ) p1 = 0.0f;
                if (c0     > row_g8) p2 = 0.0f;
                if (c0 + 1 > row_g8) p3 = 0.0f;
            }
            l0 += p0 + p1;
            l1 += p2 + p3;
            s[j][0] = p0; s[j][1] = p1; s[j][2] = p2; s[j][3] = p3;
        }

#pragma unroll
        for (int J = 0; J < 4; J++) {
            uint32_t a0 = packh2(s[2*J][0],     s[2*J][1]);
            uint32_t a1 = packh2(s[2*J][2],     s[2*J][3]);
            uint32_t a2 = packh2(s[2*J + 1][0], s[2*J + 1][1]);
            uint32_t a3 = packh2(s[2*J + 1][2], s[2*J + 1][3]);
#pragma unroll
            for (int jb = 0; jb < 16; jb++) {
                uint32_t b0 = Vs[(jb*8 + g)*VT_STR + 8*J + t];
                uint32_t b1 = Vs[(jb*8 + g)*VT_STR + 8*J + t + 4];
                mma16(accO[jb], a0, a1, a2, a3, b0, b1);
            }
        }
        __syncthreads();
    }

    l0 += __shfl_xor_sync(0xffffffffu, l0, 1);
    l0 += __shfl_xor_sync(0xffffffffu, l0, 2);
    l1 += __shfl_xor_sync(0xffffffffu, l1, 1);
    l1 += __shfl_xor_sync(0xffffffffu, l1, 2);
    const float r0 = 1.0f / l0, r1 = 1.0f / l1;

    float* outp = out + ((long)b*SS + q0 + m0 + g)*HIDD + h*DHH;
#pragma unroll
    for (int j = 0; j < 16; j++) {
        int col = j*8 + 2*t;
        *(float2*)(outp + col)          = make_float2(accO[j][0]*r0, accO[j][1]*r0);
        *(float2*)(outp + 8*HIDD + col) = make_float2(accO[j][2]*r1, accO[j][3]*r1);
    }
}

// ---------------------------------------------------------------------------
extern "C" void kernel_launch(void* const* d_in, const int* in_sizes, int n_in,
                              void* d_out, int out_size)
{
    const float* queries = (const float*)d_in[0];
    const float* Wq = (const float*)d_in[1];
    const float* bq = (const float*)d_in[2];
    const float* Wk = (const float*)d_in[3];
    const float* bk = (const float*)d_in[4];
    const float* Wv = (const float*)d_in[5];
    const float* bv = (const float*)d_in[6];
    float* out = (float*)d_out;

    cudaFuncSetAttribute(qkv_mma_kernel, cudaFuncAttributeMaxDynamicSharedMemorySize, GSM_BYTES);
    cudaFuncSetAttribute(attn_kernel, cudaFuncAttributeMaxDynamicSharedMemorySize, ASM_BYTES);

    prep_a_kernel<<<4096, 256>>>(queries);
    prep_w_kernel<<<dim3(512, 1, 3), 256>>>(Wq, Wk, Wv);
    qkv_mma_kernel<<<dim3(8, 64, 3), 128, GSM_BYTES>>>(bq, bk, bv);
    v_permute_kernel<<<dim3(16, 64), 256>>>();
    attn_kernel<<<dim3(16, 64), 128, ASM_BYTES>>>(out);
}

// round 11
// speedup vs baseline: 3.2118x; 1.0083x over previous
#include <cuda_runtime.h>
#include <cuda_fp16.h>
#include <cstdint>

#define BB 8
#define SS 1024
#define FEAT 1024
#define HIDD 1024
#define HH 8
#define DHH 128
#define MTOT (BB*SS)
#define W2R 512      // f16x2 words per token row (HIDD/2)

// f16-fragment-permuted operands for the QKV GEMM (m16n8k16 layout)
__device__ uint32_t g_Ap[MTOT/16 * FEAT/16 * 32 * 4];
__device__ uint32_t g_Wp[3][HIDD/16 * FEAT/16 * 32 * 4];
// f16x2-packed Q/K/V: [token][dim-pair word]
__device__ uint32_t g_Qh[MTOT*W2R];
__device__ uint32_t g_Kh[MTOT*W2R];
__device__ uint32_t g_Vh[MTOT*W2R];
// V transposed into token-pair pairs: [bh][dim(128)][tokenpair(512)]
__device__ uint32_t g_Vt[BB*HH*DHH*512];

__device__ __forceinline__ uint32_t packh2(float lo, float hi) {
    __half2 h = __floats2half2_rn(lo, hi);
    return *(uint32_t*)&h;
}
__device__ __forceinline__ uint32_t smaddr(const void* p) {
    return (uint32_t)__cvta_generic_to_shared(p);
}

#define CP16(dst,src) asm volatile("cp.async.cg.shared.global [%0], [%1], 16;" :: "r"(dst), "l"(src))
#define CPCOMMIT()    asm volatile("cp.async.commit_group;")
#define CPWAIT(n)     asm volatile("cp.async.wait_group %0;" :: "n"(n))

#define LDSM4(r0,r1,r2,r3,addr) \
    asm volatile("ldmatrix.sync.aligned.m8n8.x4.shared.b16 {%0,%1,%2,%3}, [%4];" \
        : "=r"(r0), "=r"(r1), "=r"(r2), "=r"(r3) : "r"(addr))

__device__ __forceinline__ void mma16(float* d, uint32_t a0, uint32_t a1,
                                      uint32_t a2, uint32_t a3,
                                      uint32_t b0, uint32_t b1) {
    asm volatile(
        "mma.sync.aligned.m16n8k16.row.col.f32.f16.f16.f32 "
        "{%0,%1,%2,%3}, {%4,%5,%6,%7}, {%8,%9}, {%0,%1,%2,%3};"
        : "+f"(d[0]), "+f"(d[1]), "+f"(d[2]), "+f"(d[3])
        : "r"(a0), "r"(a1), "r"(a2), "r"(a3), "r"(b0), "r"(b1));
}

// ---------------------------------------------------------------------------
// Prep A / Prep W (unchanged from R9)
// ---------------------------------------------------------------------------
__global__ __launch_bounds__(256)
void prep_a_kernel(const float* __restrict__ A)
{
    int idx = blockIdx.x*256 + threadIdx.x;
    int lane = idx & 31;
    int kg   = (idx >> 5) & 63;
    int mblk = idx >> 11;
    int g = lane >> 2, t = lane & 3;
    int row = 16*mblk + g, col = 16*kg + 2*t;
    const float* p0 = A + (long)row*FEAT + col;
    const float* p1 = A + (long)(row + 8)*FEAT + col;
    uint4 o;
    o.x = packh2(p0[0], p0[1]);
    o.y = packh2(p1[0], p1[1]);
    o.z = packh2(p0[8], p0[9]);
    o.w = packh2(p1[8], p1[9]);
    *(uint4*)(g_Ap + (long)idx*4) = o;
}

__global__ __launch_bounds__(256)
void prep_w_kernel(const float* __restrict__ W0, const float* __restrict__ W1,
                   const float* __restrict__ W2)
{
    const float* W = (blockIdx.z == 0) ? W0 : (blockIdx.z == 1 ? W1 : W2);
    int idx = blockIdx.x*256 + threadIdx.x;
    int lane = idx & 31;
    int kg   = (idx >> 5) & 63;
    int jp   = idx >> 11;
    int g = lane >> 2, t = lane & 3;
    int kr = 16*kg + 2*t;
    int n0 = 16*jp + g;
    uint4 o;
    o.x = packh2(W[(long)kr*HIDD + n0],       W[(long)(kr+1)*HIDD + n0]);
    o.y = packh2(W[(long)(kr+8)*HIDD + n0],   W[(long)(kr+9)*HIDD + n0]);
    o.z = packh2(W[(long)kr*HIDD + n0 + 8],   W[(long)(kr+1)*HIDD + n0 + 8]);
    o.w = packh2(W[(long)(kr+8)*HIDD + n0+8], W[(long)(kr+9)*HIDD + n0 + 8]);
    *(uint4*)(g_Wp[blockIdx.z] + (long)idx*4) = o;
}

// ---------------------------------------------------------------------------
// Pass 1: QKV projection GEMM, f16 mma.m16n8k16 (unchanged from R9).
// ---------------------------------------------------------------------------
#define QSTG_W 4096
#define GSM_BYTES (2*QSTG_W*4)

__global__ __launch_bounds__(128)
void qkv_mma_kernel(const float* __restrict__ bq, const float* __restrict__ bk,
                    const float* __restrict__ bv)
{
    extern __shared__ uint32_t smg[];
    const int tid = threadIdx.x;
    const int w = tid >> 5, lane = tid & 31;
    const int g = lane >> 2, t = lane & 3;
    const int mw = (w >> 1) * 64, nw = (w & 1) * 64;
    const int row0 = blockIdx.y * 128, col0 = blockIdx.x * 128;
    const int mb0 = row0 >> 4, jp0 = col0 >> 4;

    const uint32_t* Wp = g_Wp[blockIdx.z];
    const float* bias  = (blockIdx.z == 0) ? bq  : (blockIdx.z == 1 ? bk  : bv);
    uint32_t* Og       = (blockIdx.z == 0) ? g_Qh : (blockIdx.z == 1 ? g_Kh : g_Vh);

    float acc[4][8][4];
#pragma unroll
    for (int i = 0; i < 4; i++)
#pragma unroll
        for (int j = 0; j < 8; j++)
#pragma unroll
            for (int e = 0; e < 4; e++) acc[i][j][e] = 0.0f;

    auto issue = [&](int it) {
        uint32_t base = smaddr(smg + (it & 1)*QSTG_W);
        int kg0 = it * 2;
#pragma unroll
        for (int i = 0; i < 4; i++) {
            int c = tid + i*128;
            int mloc = c >> 6, kgl = (c >> 5) & 1, lc = c & 31;
            CP16(base + c*16,
                 g_Ap + (((long)(mb0 + mloc)*64 + kg0 + kgl)*32 + lc)*4);
        }
        uint32_t baseB = base + 2048*4;
#pragma unroll
        for (int i = 0; i < 4; i++) {
            int c = tid + i*128;
            int jloc = c >> 6, kgl = (c >> 5) & 1, lc = c & 31;
            CP16(baseB + c*16,
                 Wp + (((long)(jp0 + jloc)*64 + kg0 + kgl)*32 + lc)*4);
        }
    };

    issue(0); CPCOMMIT();
    for (int it = 0; it < 32; ++it) {
        if (it + 1 < 32) issue(it + 1);
        CPCOMMIT();
        CPWAIT(1);
        __syncthreads();
        const uint32_t* As = smg + (it & 1)*QSTG_W;
        const uint32_t* Bs = As + 2048;
#pragma unroll
        for (int kgl = 0; kgl < 2; kgl++) {
            uint32_t a[4][4], b[4][4];
#pragma unroll
            for (int i = 0; i < 4; i++) {
                int mloc = (mw >> 4) + i;
                *(uint4*)a[i] = *(const uint4*)(As + ((mloc*2 + kgl)*32 + lane)*4);
            }
#pragma unroll
            for (int jp = 0; jp < 4; jp++) {
                int jloc = (nw >> 4) + jp;
                *(uint4*)b[jp] = *(const uint4*)(Bs + ((jloc*2 + kgl)*32 + lane)*4);
            }
#pragma unroll
            for (int i = 0; i < 4; i++)
#pragma unroll
                for (int jp = 0; jp < 4; jp++) {
                    mma16(acc[i][2*jp],     a[i][0], a[i][1], a[i][2], a[i][3],
                          b[jp][0], b[jp][1]);
                    mma16(acc[i][2*jp + 1], a[i][0], a[i][1], a[i][2], a[i][3],
                          b[jp][2], b[jp][3]);
                }
        }
        __syncthreads();
    }

#pragma unroll
    for (int j = 0; j < 8; j++) {
        int col = col0 + nw + j*8 + 2*t;
        int colw = ((col0 + nw + j*8) >> 1) + t;
        float b0 = bias[col], b1 = bias[col + 1];
#pragma unroll
        for (int i = 0; i < 4; i++) {
            int row = row0 + mw + i*16 + g;
            Og[(long)row*W2R + colw]       = packh2(acc[i][j][0] + b0, acc[i][j][1] + b1);
            Og[(long)(row + 8)*W2R + colw] = packh2(acc[i][j][2] + b0, acc[i][j][3] + b1);
        }
    }
}

// ---------------------------------------------------------------------------
// V permute (unchanged from R8)
// ---------------------------------------------------------------------------
__global__ __launch_bounds__(256)
void v_permute_kernel()
{
    __shared__ uint32_t sv[64*65];
    const int tid = threadIdx.x;
    const int bh = blockIdx.y, b = bh >> 3, h = bh & 7;
    const int tok0 = blockIdx.x * 64, tp0 = blockIdx.x * 32;

#pragma unroll
    for (int i = 0; i < 16; i++) {
        int idx = tid + i*256;
        int r = idx >> 6, wd = idx & 63;
        sv[r*65 + wd] = g_Vh[((long)(b*SS + tok0 + r))*W2R + h*64 + wd];
    }
    __syncthreads();
#pragma unroll
    for (int i = 0; i < 16; i++) {
        int idx = tid + i*256;
        int dim = idx >> 5, tpl = idx & 31;
        uint32_t w0 = sv[(2*tpl)*65 + (dim >> 1)];
        uint32_t w1 = sv[(2*tpl + 1)*65 + (dim >> 1)];
        uint32_t o = (dim & 1) ? __byte_perm(w0, w1, 0x7632)
                               : __byte_perm(w0, w1, 0x5410);
        g_Vt[((long)bh*DHH + dim)*512 + tp0 + tpl] = o;
    }
}

// ---------------------------------------------------------------------------
// Pass 2: causal attention, f16 mma, register-resident P, ldmatrix B-loads.
// 128 threads (4 warps), q-tile 64, 2 CTAs/SM.
// ---------------------------------------------------------------------------
#define KH_STR 68
#define VT_STR 36
#define KTILE_W (64*KH_STR)
#define VTILE_W (128*VT_STR)
#define STAGE_W (KTILE_W + VTILE_W)
#define ASM_BYTES (2*STAGE_W*4)           // 71,680 B per CTA

__global__ __launch_bounds__(128, 2)
void attn_kernel(float* __restrict__ out)
{
    extern __shared__ uint32_t sm[];

    const int tid = threadIdx.x;
    const int w = tid >> 5, lane = tid & 31;
    const int g = lane >> 2, t = lane & 3;
    const int m0 = w * 16;
    const int qt = 15 - blockIdx.x;           // biggest blocks first
    const int q0 = qt * 64;
    const int bh = blockIdx.y, b = bh >> 3, h = bh & 7;
    const int nk = qt + 1;

    const uint32_t* Qg = g_Qh + (long)b*SS*W2R + h*64;
    const uint32_t* Kg = g_Kh + (long)b*SS*W2R + h*64;
    const uint32_t* Vtg = g_Vt + (long)bh*DHH*512;

    // ldmatrix per-lane address offsets (within a tile, in bytes)
    // B-pair matrices: (j,kh0),(j,kh1),(j+1,kh0),(j+1,kh1)
    const uint32_t kOff = (uint32_t)((((lane >> 4)*8 + (lane & 7))*KH_STR)*4
                                     + ((lane >> 3) & 1)*16);
    const uint32_t vOff = (uint32_t)((((lane >> 4)*8 + (lane & 7))*VT_STR)*4
                                     + ((lane >> 3) & 1)*16);
    // A matrices: (rows 0-7,kh0),(rows 8-15,kh0),(rows 0-7,kh1),(rows 8-15,kh1)
    const uint32_t aOff = (uint32_t)(((m0 + (lane & 7) + ((lane >> 3) & 1)*8)*KH_STR)*4
                                     + (lane >> 4)*16);

    // stage Q tile [64 tok x 64 words]
    {
        uint32_t base = smaddr(sm);
#pragma unroll
        for (int i = 0; i < 8; i++) {
            int c = tid + i*128;               // 0..1023
            int r = c >> 4, part = c & 15;
            CP16(base + (r*KH_STR + part*4)*4, Qg + (long)(q0 + r)*W2R + part*4);
        }
        CPCOMMIT(); CPWAIT(0);
    }
    __syncthreads();

    uint32_t aQ[8][4];
    {
        uint32_t baseA = smaddr(sm) + aOff;
#pragma unroll
        for (int K = 0; K < 8; K++)
            LDSM4(aQ[K][0], aQ[K][1], aQ[K][2], aQ[K][3], baseA + K*32);
    }
    __syncthreads();

    float accO[16][4];
#pragma unroll
    for (int j = 0; j < 16; j++)
#pragma unroll
        for (int e = 0; e < 4; e++) accO[j][e] = 0.0f;
    float l0 = 0.0f, l1 = 0.0f;
    const float scl = 0.08838834764831843f;
    const float LN16 = 2.772588722239781f;

    auto issue = [&](int kt) {
        uint32_t baseK = smaddr(sm + (kt & 1)*STAGE_W);
        uint32_t baseV = baseK + KTILE_W*4;
        int k0 = kt * 64;
#pragma unroll
        for (int i = 0; i < 8; i++) {
            int c = tid + i*128;               // 0..1023  K fill
            int r = c >> 4, part = c & 15;
            CP16(baseK + (r*KH_STR + part*4)*4, Kg + (long)(k0 + r)*W2R + part*4);
        }
#pragma unroll
        for (int i = 0; i < 8; i++) {
            int c = tid + i*128;               // 0..1023  V fill
            int dim = c >> 3, part = c & 7;
            CP16(baseV + (dim*VT_STR + part*4)*4,
                 Vtg + (long)dim*512 + kt*32 + part*4);
        }
    };

    issue(0); CPCOMMIT();
    for (int kt = 0; kt < nk; kt++) {
        if (kt + 1 < nk) issue(kt + 1);
        CPCOMMIT();
        CPWAIT(1);
        __syncthreads();
        const uint32_t stg = smaddr(sm + (kt & 1)*STAGE_W);
        const uint32_t kBase = stg + kOff;
        const uint32_t vBase = stg + KTILE_W*4 + vOff;
        const int k0 = kt * 64;

        // S = Q K^T : per kgroup, 4 ldmatrix.x4 cover all 8 token-blocks
        float s[8][4];
#pragma unroll
        for (int j = 0; j < 8; j++)
#pragma unroll
            for (int e = 0; e < 4; e++) s[j][e] = 0.0f;
#pragma unroll
        for (int K = 0; K < 8; K++) {
#pragma unroll
            for (int jp2 = 0; jp2 < 4; jp2++) {
                uint32_t b0, b1, b2, b3;
                LDSM4(b0, b1, b2, b3, kBase + jp2*(16*KH_STR*4) + K*32);
                mma16(s[2*jp2],     aQ[K][0], aQ[K][1], aQ[K][2], aQ[K][3], b0, b1);
                mma16(s[2*jp2 + 1], aQ[K][0], aQ[K][1], aQ[K][2], aQ[K][3], b2, b3);
            }
        }

        // p = exp(exp(s/sqrt(d)) - ln16), causal mask near diagonal
        const int row_g  = q0 + m0 + g;
        const int row_g8 = row_g + 8;
        const bool diag = (k0 + 63 > row_g);
#pragma unroll
        for (int j = 0; j < 8; j++) {
            int c0 = k0 + j*8 + 2*t;
            float y0 = __expf(s[j][0]*scl), y1 = __expf(s[j][1]*scl);
            float y2 = __expf(s[j][2]*scl), y3 = __expf(s[j][3]*scl);
            float p0 = __expf(y0 - LN16), p1 = __expf(y1 - LN16);
            float p2 = __expf(y2 - LN16), p3 = __expf(y3 - LN16);
            if (diag) {
                if (c0     > row_g ) p0 = 0.0f;
                if (c0 + 1 > row_g ) p1 = 0.0f;
                if (c0     > row_g8) p2 = 0.0f;
                if (c0 + 1 > row_g8) p3 = 0.0f;
            }
            l0 += p0 + p1;
            l1 += p2 + p3;
            s[j][0] = p0; s[j][1] = p1; s[j][2] = p2; s[j][3] = p3;
        }

        // O += P V : per J, 8 ldmatrix.x4 cover all 16 dim-blocks
#pragma unroll
        for (int J = 0; J < 4; J++) {
            uint32_t a0 = packh2(s[2*J][0],     s[2*J][1]);
            uint32_t a1 = packh2(s[2*J][2],     s[2*J][3]);
            uint32_t a2 = packh2(s[2*J + 1][0], s[2*J + 1][1]);
            uint32_t a3 = packh2(s[2*J + 1][2], s[2*J + 1][3]);
#pragma unroll
            for (int jbp = 0; jbp < 8; jbp++) {
                uint32_t b0, b1, b2, b3;
                LDSM4(b0, b1, b2, b3, vBase + jbp*(16*VT_STR*4) + J*32);
                mma16(accO[2*jbp],     a0, a1, a2, a3, b0, b1);
                mma16(accO[2*jbp + 1], a0, a1, a2, a3, b2, b3);
            }
        }
        __syncthreads();
    }

    l0 += __shfl_xor_sync(0xffffffffu, l0, 1);
    l0 += __shfl_xor_sync(0xffffffffu, l0, 2);
    l1 += __shfl_xor_sync(0xffffffffu, l1, 1);
    l1 += __shfl_xor_sync(0xffffffffu, l1, 2);
    const float r0 = 1.0f / l0, r1 = 1.0f / l1;

    float* outp = out + ((long)b*SS + q0 + m0 + g)*HIDD + h*DHH;
#pragma unroll
    for (int j = 0; j < 16; j++) {
        int col = j*8 + 2*t;
        *(float2*)(outp + col)          = make_float2(accO[j][0]*r0, accO[j][1]*r0);
        *(float2*)(outp + 8*HIDD + col) = make_float2(accO[j][2]*r1, accO[j][3]*r1);
    }
}

// ---------------------------------------------------------------------------
extern "C" void kernel_launch(void* const* d_in, const int* in_sizes, int n_in,
                              void* d_out, int out_size)
{
    const float* queries = (const float*)d_in[0];
    const float* Wq = (const float*)d_in[1];
    const float* bq = (const float*)d_in[2];
    const float* Wk = (const float*)d_in[3];
    const float* bk = (const float*)d_in[4];
    const float* Wv = (const float*)d_in[5];
    const float* bv = (const float*)d_in[6];
    float* out = (float*)d_out;

    cudaFuncSetAttribute(qkv_mma_kernel, cudaFuncAttributeMaxDynamicSharedMemorySize, GSM_BYTES);
    cudaFuncSetAttribute(attn_kernel, cudaFuncAttributeMaxDynamicSharedMemorySize, ASM_BYTES);

    prep_a_kernel<<<4096, 256>>>(queries);
    prep_w_kernel<<<dim3(512, 1, 3), 256>>>(Wq, Wk, Wv);
    qkv_mma_kernel<<<dim3(8, 64, 3), 128, GSM_BYTES>>>(bq, bk, bv);
    v_permute_kernel<<<dim3(16, 64), 256>>>();
    attn_kernel<<<dim3(16, 64), 128, ASM_BYTES>>>(out);
}

// round 12
// speedup vs baseline: 3.2328x; 1.0065x over previous
#include <cuda_runtime.h>
#include <cuda_fp16.h>
#include <cstdint>

#define BB 8
#define SS 1024
#define FEAT 1024
#define HIDD 1024
#define HH 8
#define DHH 128
#define MTOT (BB*SS)
#define W2R 512      // f16x2 words per token row (HIDD/2)

// f16-fragment-permuted operands for the QKV GEMM (m16n8k16 layout)
__device__ uint32_t g_Ap[MTOT/16 * FEAT/16 * 32 * 4];
__device__ uint32_t g_Wp[3][HIDD/16 * FEAT/16 * 32 * 4];
// f16x2-packed Q/K: [token][dim-pair word]
__device__ uint32_t g_Qh[MTOT*W2R];
__device__ uint32_t g_Kh[MTOT*W2R];
// V transposed into token-pair pairs: [bh][dim(128)][tokenpair(512)]
__device__ uint32_t g_Vt[BB*HH*DHH*512];

__device__ __forceinline__ uint32_t packh2(float lo, float hi) {
    __half2 h = __floats2half2_rn(lo, hi);
    return *(uint32_t*)&h;
}
__device__ __forceinline__ uint32_t smaddr(const void* p) {
    return (uint32_t)__cvta_generic_to_shared(p);
}

#define CP16(dst,src) asm volatile("cp.async.cg.shared.global [%0], [%1], 16;" :: "r"(dst), "l"(src))
#define CPCOMMIT()    asm volatile("cp.async.commit_group;")
#define CPWAIT(n)     asm volatile("cp.async.wait_group %0;" :: "n"(n))

#define LDSM4(r0,r1,r2,r3,addr) \
    asm volatile("ldmatrix.sync.aligned.m8n8.x4.shared.b16 {%0,%1,%2,%3}, [%4];" \
        : "=r"(r0), "=r"(r1), "=r"(r2), "=r"(r3) : "r"(addr))

__device__ __forceinline__ void mma16(float* d, uint32_t a0, uint32_t a1,
                                      uint32_t a2, uint32_t a3,
                                      uint32_t b0, uint32_t b1) {
    asm volatile(
        "mma.sync.aligned.m16n8k16.row.col.f32.f16.f16.f32 "
        "{%0,%1,%2,%3}, {%4,%5,%6,%7}, {%8,%9}, {%0,%1,%2,%3};"
        : "+f"(d[0]), "+f"(d[1]), "+f"(d[2]), "+f"(d[3])
        : "r"(a0), "r"(a1), "r"(a2), "r"(a3), "r"(b0), "r"(b1));
}

// ---------------------------------------------------------------------------
// Prep A / Prep W (unchanged)
// ---------------------------------------------------------------------------
__global__ __launch_bounds__(256)
void prep_a_kernel(const float* __restrict__ A)
{
    int idx = blockIdx.x*256 + threadIdx.x;
    int lane = idx & 31;
    int kg   = (idx >> 5) & 63;
    int mblk = idx >> 11;
    int g = lane >> 2, t = lane & 3;
    int row = 16*mblk + g, col = 16*kg + 2*t;
    const float* p0 = A + (long)row*FEAT + col;
    const float* p1 = A + (long)(row + 8)*FEAT + col;
    uint4 o;
    o.x = packh2(p0[0], p0[1]);
    o.y = packh2(p1[0], p1[1]);
    o.z = packh2(p0[8], p0[9]);
    o.w = packh2(p1[8], p1[9]);
    *(uint4*)(g_Ap + (long)idx*4) = o;
}

__global__ __launch_bounds__(256)
void prep_w_kernel(const float* __restrict__ W0, const float* __restrict__ W1,
                   const float* __restrict__ W2)
{
    const float* W = (blockIdx.z == 0) ? W0 : (blockIdx.z == 1 ? W1 : W2);
    int idx = blockIdx.x*256 + threadIdx.x;
    int lane = idx & 31;
    int kg   = (idx >> 5) & 63;
    int jp   = idx >> 11;
    int g = lane >> 2, t = lane & 3;
    int kr = 16*kg + 2*t;
    int n0 = 16*jp + g;
    uint4 o;
    o.x = packh2(W[(long)kr*HIDD + n0],       W[(long)(kr+1)*HIDD + n0]);
    o.y = packh2(W[(long)(kr+8)*HIDD + n0],   W[(long)(kr+9)*HIDD + n0]);
    o.z = packh2(W[(long)kr*HIDD + n0 + 8],   W[(long)(kr+1)*HIDD + n0 + 8]);
    o.w = packh2(W[(long)(kr+8)*HIDD + n0+8], W[(long)(kr+9)*HIDD + n0 + 8]);
    *(uint4*)(g_Wp[blockIdx.z] + (long)idx*4) = o;
}

// ---------------------------------------------------------------------------
// Pass 1: QKV projection GEMM, f16 mma.m16n8k16.
// NOW: 256 threads (8 warps x 32x64 warp tile), 2 CTAs/SM.
// z==2 (V) epilogue transposes in smem and writes g_Vt directly.
// ---------------------------------------------------------------------------
#define QSTG_W 4096                       // words per stage (A 2048 + B 2048)
#define GSM_BYTES (128*65*4)              // 33280 >= 2 stages (32768)

__global__ __launch_bounds__(256, 2)
void qkv_mma_kernel(const float* __restrict__ bq, const float* __restrict__ bk,
                    const float* __restrict__ bv)
{
    extern __shared__ uint32_t smg[];
    const int tid = threadIdx.x;
    const int w = tid >> 5, lane = tid & 31;
    const int g = lane >> 2, t = lane & 3;
    const int mw = (w & 3) * 32, nw = (w >> 2) * 64;   // warp tile origin
    const int row0 = blockIdx.y * 128, col0 = blockIdx.x * 128;
    const int mb0 = row0 >> 4, jp0 = col0 >> 4;
    const int z = blockIdx.z;

    const uint32_t* Wp = g_Wp[z];
    const float* bias  = (z == 0) ? bq  : (z == 1 ? bk  : bv);

    float acc[2][8][4];
#pragma unroll
    for (int i = 0; i < 2; i++)
#pragma unroll
        for (int j = 0; j < 8; j++)
#pragma unroll
            for (int e = 0; e < 4; e++) acc[i][j][e] = 0.0f;

    auto issue = [&](int it) {
        uint32_t base = smaddr(smg + (it & 1)*QSTG_W);
        int kg0 = it * 2;
#pragma unroll
        for (int i = 0; i < 2; i++) {
            int c = tid + i*256;                 // 0..511
            int mloc = c >> 6, kgl = (c >> 5) & 1, lc = c & 31;
            CP16(base + c*16,
                 g_Ap + (((long)(mb0 + mloc)*64 + kg0 + kgl)*32 + lc)*4);
        }
        uint32_t baseB = base + 2048*4;
#pragma unroll
        for (int i = 0; i < 2; i++) {
            int c = tid + i*256;
            int jloc = c >> 6, kgl = (c >> 5) & 1, lc = c & 31;
            CP16(baseB + c*16,
                 Wp + (((long)(jp0 + jloc)*64 + kg0 + kgl)*32 + lc)*4);
        }
    };

    issue(0); CPCOMMIT();
    for (int it = 0; it < 32; ++it) {
        if (it + 1 < 32) issue(it + 1);
        CPCOMMIT();
        CPWAIT(1);
        __syncthreads();
        const uint32_t* As = smg + (it & 1)*QSTG_W;
        const uint32_t* Bs = As + 2048;
#pragma unroll
        for (int kgl = 0; kgl < 2; kgl++) {
            uint32_t a[2][4], b[4][4];
#pragma unroll
            for (int i = 0; i < 2; i++) {
                int mloc = (mw >> 4) + i;
                *(uint4*)a[i] = *(const uint4*)(As + ((mloc*2 + kgl)*32 + lane)*4);
            }
#pragma unroll
            for (int jp = 0; jp < 4; jp++) {
                int jloc = (nw >> 4) + jp;
                *(uint4*)b[jp] = *(const uint4*)(Bs + ((jloc*2 + kgl)*32 + lane)*4);
            }
#pragma unroll
            for (int i = 0; i < 2; i++)
#pragma unroll
                for (int jp = 0; jp < 4; jp++) {
                    mma16(acc[i][2*jp],     a[i][0], a[i][1], a[i][2], a[i][3],
                          b[jp][0], b[jp][1]);
                    mma16(acc[i][2*jp + 1], a[i][0], a[i][1], a[i][2], a[i][3],
                          b[jp][2], b[jp][3]);
                }
        }
        __syncthreads();
    }

    if (z < 2) {
        // Q/K epilogue: + bias, pack f16x2, store [token][dimpair]
        uint32_t* Og = (z == 0) ? g_Qh : g_Kh;
#pragma unroll
        for (int j = 0; j < 8; j++) {
            int col = col0 + nw + j*8 + 2*t;
            int colw = ((col0 + nw + j*8) >> 1) + t;
            float b0 = bias[col], b1 = bias[col + 1];
#pragma unroll
            for (int i = 0; i < 2; i++) {
                int row = row0 + mw + i*16 + g;
                Og[(long)row*W2R + colw]       = packh2(acc[i][j][0] + b0, acc[i][j][1] + b1);
                Og[(long)(row + 8)*W2R + colw] = packh2(acc[i][j][2] + b0, acc[i][j][3] + b1);
            }
        }
    } else {
        // V epilogue: stage [token_local][dimpair] in smem, then write g_Vt
        uint32_t* sv = smg;                        // 128 x 65 words
#pragma unroll
        for (int j = 0; j < 8; j++) {
            int col = col0 + nw + j*8 + 2*t;
            int dpl = ((nw + j*8) >> 1) + t;       // local dim-pair 0..63
            float b0 = bias[col], b1 = bias[col + 1];
#pragma unroll
            for (int i = 0; i < 2; i++) {
                int tokl = mw + i*16 + g;
                sv[tokl*65 + dpl]       = packh2(acc[i][j][0] + b0, acc[i][j][1] + b1);
                sv[(tokl + 8)*65 + dpl] = packh2(acc[i][j][2] + b0, acc[i][j][3] + b1);
            }
        }
        __syncthreads();

        const int b = row0 >> 10;                  // batch
        const int t0 = row0 & 1023;                // token offset within batch
        const int bh = b*HH + blockIdx.x;          // col block == head
        uint32_t* dst = g_Vt + ((long)bh*DHH)*512 + (t0 >> 1);
#pragma unroll
        for (int i = 0; i < 32; i++) {
            int idx = tid + i*256;                 // 0..8191
            int dim = idx >> 6, tpl = idx & 63;
            uint32_t w0 = sv[(2*tpl)*65 + (dim >> 1)];
            uint32_t w1 = sv[(2*tpl + 1)*65 + (dim >> 1)];
            uint32_t o = (dim & 1) ? __byte_perm(w0, w1, 0x7632)
                                   : __byte_perm(w0, w1, 0x5410);
            dst[(long)dim*512 + tpl] = o;
        }
    }
}

// ---------------------------------------------------------------------------
// Pass 2: causal attention (unchanged from R11).
// ---------------------------------------------------------------------------
#define KH_STR 68
#define VT_STR 36
#define KTILE_W (64*KH_STR)
#define VTILE_W (128*VT_STR)
#define STAGE_W (KTILE_W + VTILE_W)
#define ASM_BYTES (2*STAGE_W*4)           // 71,680 B per CTA

__global__ __launch_bounds__(128, 2)
void attn_kernel(float* __restrict__ out)
{
    extern __shared__ uint32_t sm[];

    const int tid = threadIdx.x;
    const int w = tid >> 5, lane = tid & 31;
    const int g = lane >> 2, t = lane & 3;
    const int m0 = w * 16;
    const int qt = 15 - blockIdx.x;
    const int q0 = qt * 64;
    const int bh = blockIdx.y, b = bh >> 3, h = bh & 7;
    const int nk = qt + 1;

    const uint32_t* Qg = g_Qh + (long)b*SS*W2R + h*64;
    const uint32_t* Kg = g_Kh + (long)b*SS*W2R + h*64;
    const uint32_t* Vtg = g_Vt + (long)bh*DHH*512;

    const uint32_t kOff = (uint32_t)((((lane >> 4)*8 + (lane & 7))*KH_STR)*4
                                     + ((lane >> 3) & 1)*16);
    const uint32_t vOff = (uint32_t)((((lane >> 4)*8 + (lane & 7))*VT_STR)*4
                                     + ((lane >> 3) & 1)*16);
    const uint32_t aOff = (uint32_t)(((m0 + (lane & 7) + ((lane >> 3) & 1)*8)*KH_STR)*4
                                     + (lane >> 4)*16);

    {
        uint32_t base = smaddr(sm);
#pragma unroll
        for (int i = 0; i < 8; i++) {
            int c = tid + i*128;
            int r = c >> 4, part = c & 15;
            CP16(base + (r*KH_STR + part*4)*4, Qg + (long)(q0 + r)*W2R + part*4);
        }
        CPCOMMIT(); CPWAIT(0);
    }
    __syncthreads();

    uint32_t aQ[8][4];
    {
        uint32_t baseA = smaddr(sm) + aOff;
#pragma unroll
        for (int K = 0; K < 8; K++)
            LDSM4(aQ[K][0], aQ[K][1], aQ[K][2], aQ[K][3], baseA + K*32);
    }
    __syncthreads();

    float accO[16][4];
#pragma unroll
    for (int j = 0; j < 16; j++)
#pragma unroll
        for (int e = 0; e < 4; e++) accO[j][e] = 0.0f;
    float l0 = 0.0f, l1 = 0.0f;
    const float scl = 0.08838834764831843f;
    const float LN16 = 2.772588722239781f;

    auto issue = [&](int kt) {
        uint32_t baseK = smaddr(sm + (kt & 1)*STAGE_W);
        uint32_t baseV = baseK + KTILE_W*4;
        int k0 = kt * 64;
#pragma unroll
        for (int i = 0; i < 8; i++) {
            int c = tid + i*128;
            int r = c >> 4, part = c & 15;
            CP16(baseK + (r*KH_STR + part*4)*4, Kg + (long)(k0 + r)*W2R + part*4);
        }
#pragma unroll
        for (int i = 0; i < 8; i++) {
            int c = tid + i*128;
            int dim = c >> 3, part = c & 7;
            CP16(baseV + (dim*VT_STR + part*4)*4,
                 Vtg + (long)dim*512 + kt*32 + part*4);
        }
    };

    issue(0); CPCOMMIT();
    for (int kt = 0; kt < nk; kt++) {
        if (kt + 1 < nk) issue(kt + 1);
        CPCOMMIT();
        CPWAIT(1);
        __syncthreads();
        const uint32_t stg = smaddr(sm + (kt & 1)*STAGE_W);
        const uint32_t kBase = stg + kOff;
        const uint32_t vBase = stg + KTILE_W*4 + vOff;
        const int k0 = kt * 64;

        float s[8][4];
#pragma unroll
        for (int j = 0; j < 8; j++)
#pragma unroll
            for (int e = 0; e < 4; e++) s[j][e] = 0.0f;
#pragma unroll
        for (int K = 0; K < 8; K++) {
#pragma unroll
            for (int jp2 = 0; jp2 < 4; jp2++) {
                uint32_t b0, b1, b2, b3;
                LDSM4(b0, b1, b2, b3, kBase + jp2*(16*KH_STR*4) + K*32);
                mma16(s[2*jp2],     aQ[K][0], aQ[K][1], aQ[K][2], aQ[K][3], b0, b1);
                mma16(s[2*jp2 + 1], aQ[K][0], aQ[K][1], aQ[K][2], aQ[K][3], b2, b3);
            }
        }

        const int row_g  = q0 + m0 + g;
        const int row_g8 = row_g + 8;
        const bool diag = (k0 + 63 > row_g);
#pragma unroll
        for (int j = 0; j < 8; j++) {
            int c0 = k0 + j*8 + 2*t;
            float y0 = __expf(s[j][0]*scl), y1 = __expf(s[j][1]*scl);
            float y2 = __expf(s[j][2]*scl), y3 = __expf(s[j][3]*scl);
            float p0 = __expf(y0 - LN16), p1 = __expf(y1 - LN16);
            float p2 = __expf(y2 - LN16), p3 = __expf(y3 - LN16);
            if (diag) {
                if (c0     > row_g ) p0 = 0.0f;
                if (c0 + 1 > row_g ) p1 = 0.0f;
                if (c0     > row_g8) p2 = 0.0f;
                if (c0 + 1 > row_g8) p3 = 0.0f;
            }
            l0 += p0 + p1;
            l1 += p2 + p3;
            s[j][0] = p0; s[j][1] = p1; s[j][2] = p2; s[j][3] = p3;
        }

#pragma unroll
        for (int J = 0; J < 4; J++) {
            uint32_t a0 = packh2(s[2*J][0],     s[2*J][1]);
            uint32_t a1 = packh2(s[2*J][2],     s[2*J][3]);
            uint32_t a2 = packh2(s[2*J + 1][0], s[2*J + 1][1]);
            uint32_t a3 = packh2(s[2*J + 1][2], s[2*J + 1][3]);
#pragma unroll
            for (int jbp = 0; jbp < 8; jbp++) {
                uint32_t b0, b1, b2, b3;
                LDSM4(b0, b1, b2, b3, vBase + jbp*(16*VT_STR*4) + J*32);
                mma16(accO[2*jbp],     a0, a1, a2, a3, b0, b1);
                mma16(accO[2*jbp + 1], a0, a1, a2, a3, b2, b3);
            }
        }
        __syncthreads();
    }

    l0 += __shfl_xor_sync(0xffffffffu, l0, 1);
    l0 += __shfl_xor_sync(0xffffffffu, l0, 2);
    l1 += __shfl_xor_sync(0xffffffffu, l1, 1);
    l1 += __shfl_xor_sync(0xffffffffu, l1, 2);
    const float r0 = 1.0f / l0, r1 = 1.0f / l1;

    float* outp = out + ((long)b*SS + q0 + m0 + g)*HIDD + h*DHH;
#pragma unroll
    for (int j = 0; j < 16; j++) {
        int col = j*8 + 2*t;
        *(float2*)(outp + col)          = make_float2(accO[j][0]*r0, accO[j][1]*r0);
        *(float2*)(outp + 8*HIDD + col) = make_float2(accO[j][2]*r1, accO[j][3]*r1);
    }
}

// ---------------------------------------------------------------------------
extern "C" void kernel_launch(void* const* d_in, const int* in_sizes, int n_in,
                              void* d_out, int out_size)
{
    const float* queries = (const float*)d_in[0];
    const float* Wq = (const float*)d_in[1];
    const float* bq = (const float*)d_in[2];
    const float* Wk = (const float*)d_in[3];
    const float* bk = (const float*)d_in[4];
    const float* Wv = (const float*)d_in[5];
    const float* bv = (const float*)d_in[6];
    float* out = (float*)d_out;

    cudaFuncSetAttribute(qkv_mma_kernel, cudaFuncAttributeMaxDynamicSharedMemorySize, GSM_BYTES);
    cudaFuncSetAttribute(attn_kernel, cudaFuncAttributeMaxDynamicSharedMemorySize, ASM_BYTES);

    prep_a_kernel<<<4096, 256>>>(queries);
    prep_w_kernel<<<dim3(512, 1, 3), 256>>>(Wq, Wk, Wv);
    qkv_mma_kernel<<<dim3(8, 64, 3), 256, GSM_BYTES>>>(bq, bk, bv);
    attn_kernel<<<dim3(16, 64), 128, ASM_BYTES>>>(out);
}

// round 13
// speedup vs baseline: 3.3143x; 1.0252x over previous
#include <cuda_runtime.h>
#include <cuda_fp16.h>
#include <cstdint>

#define BB 8
#define SS 1024
#define FEAT 1024
#define HIDD 1024
#define HH 8
#define DHH 128
#define MTOT (BB*SS)
#define W2R 512      // f16x2 words per token row (HIDD/2)

// f16-fragment-permuted operands for the QKV GEMM (m16n8k16 layout)
__device__ uint32_t g_Ap[MTOT/16 * FEAT/16 * 32 * 4];
__device__ uint32_t g_Wp[3][HIDD/16 * FEAT/16 * 32 * 4];
// f16x2-packed Q/K: [token][dim-pair word]
__device__ uint32_t g_Qh[MTOT*W2R];
__device__ uint32_t g_Kh[MTOT*W2R];
// V transposed into token-pair pairs: [bh][dim(128)][tokenpair(512)]
__device__ uint32_t g_Vt[BB*HH*DHH*512];

__device__ __forceinline__ uint32_t packh2(float lo, float hi) {
    __half2 h = __floats2half2_rn(lo, hi);
    return *(uint32_t*)&h;
}
__device__ __forceinline__ uint32_t smaddr(const void* p) {
    return (uint32_t)__cvta_generic_to_shared(p);
}

#define CP16(dst,src) asm volatile("cp.async.cg.shared.global [%0], [%1], 16;" :: "r"(dst), "l"(src))
#define CPCOMMIT()    asm volatile("cp.async.commit_group;")
#define CPWAIT(n)     asm volatile("cp.async.wait_group %0;" :: "n"(n))

#define LDSM4(r0,r1,r2,r3,addr) \
    asm volatile("ldmatrix.sync.aligned.m8n8.x4.shared.b16 {%0,%1,%2,%3}, [%4];" \
        : "=r"(r0), "=r"(r1), "=r"(r2), "=r"(r3) : "r"(addr))

__device__ __forceinline__ void mma16(float* d, uint32_t a0, uint32_t a1,
                                      uint32_t a2, uint32_t a3,
                                      uint32_t b0, uint32_t b1) {
    asm volatile(
        "mma.sync.aligned.m16n8k16.row.col.f32.f16.f16.f32 "
        "{%0,%1,%2,%3}, {%4,%5,%6,%7}, {%8,%9}, {%0,%1,%2,%3};"
        : "+f"(d[0]), "+f"(d[1]), "+f"(d[2]), "+f"(d[3])
        : "r"(a0), "r"(a1), "r"(a2), "r"(a3), "r"(b0), "r"(b1));
}

// ---------------------------------------------------------------------------
// Prep A / Prep W (unchanged)
// ---------------------------------------------------------------------------
__global__ __launch_bounds__(256)
void prep_a_kernel(const float* __restrict__ A)
{
    int idx = blockIdx.x*256 + threadIdx.x;
    int lane = idx & 31;
    int kg   = (idx >> 5) & 63;
    int mblk = idx >> 11;
    int g = lane >> 2, t = lane & 3;
    int row = 16*mblk + g, col = 16*kg + 2*t;
    const float* p0 = A + (long)row*FEAT + col;
    const float* p1 = A + (long)(row + 8)*FEAT + col;
    uint4 o;
    o.x = packh2(p0[0], p0[1]);
    o.y = packh2(p1[0], p1[1]);
    o.z = packh2(p0[8], p0[9]);
    o.w = packh2(p1[8], p1[9]);
    *(uint4*)(g_Ap + (long)idx*4) = o;
}

__global__ __launch_bounds__(256)
void prep_w_kernel(const float* __restrict__ W0, const float* __restrict__ W1,
                   const float* __restrict__ W2)
{
    const float* W = (blockIdx.z == 0) ? W0 : (blockIdx.z == 1 ? W1 : W2);
    int idx = blockIdx.x*256 + threadIdx.x;
    int lane = idx & 31;
    int kg   = (idx >> 5) & 63;
    int jp   = idx >> 11;
    int g = lane >> 2, t = lane & 3;
    int kr = 16*kg + 2*t;
    int n0 = 16*jp + g;
    uint4 o;
    o.x = packh2(W[(long)kr*HIDD + n0],       W[(long)(kr+1)*HIDD + n0]);
    o.y = packh2(W[(long)(kr+8)*HIDD + n0],   W[(long)(kr+9)*HIDD + n0]);
    o.z = packh2(W[(long)kr*HIDD + n0 + 8],   W[(long)(kr+1)*HIDD + n0 + 8]);
    o.w = packh2(W[(long)(kr+8)*HIDD + n0+8], W[(long)(kr+9)*HIDD + n0 + 8]);
    *(uint4*)(g_Wp[blockIdx.z] + (long)idx*4) = o;
}

// ---------------------------------------------------------------------------
// Pass 1: QKV projection GEMM, f16 mma.m16n8k16 (R9 mainloop: 128 threads,
// 4 warps x 64x64). z==2 (V) epilogue transposes in smem -> g_Vt directly.
// ---------------------------------------------------------------------------
#define QSTG_W 4096                       // words per stage (A 2048 + B 2048)
#define GSM_BYTES (128*65*4)              // 33280 B >= 2 stages (32768)

__global__ __launch_bounds__(128)
void qkv_mma_kernel(const float* __restrict__ bq, const float* __restrict__ bk,
                    const float* __restrict__ bv)
{
    extern __shared__ uint32_t smg[];
    const int tid = threadIdx.x;
    const int w = tid >> 5, lane = tid & 31;
    const int g = lane >> 2, t = lane & 3;
    const int mw = (w >> 1) * 64, nw = (w & 1) * 64;
    const int row0 = blockIdx.y * 128, col0 = blockIdx.x * 128;
    const int mb0 = row0 >> 4, jp0 = col0 >> 4;
    const int z = blockIdx.z;

    const uint32_t* Wp = g_Wp[z];
    const float* bias  = (z == 0) ? bq : (z == 1 ? bk : bv);

    float acc[4][8][4];
#pragma unroll
    for (int i = 0; i < 4; i++)
#pragma unroll
        for (int j = 0; j < 8; j++)
#pragma unroll
            for (int e = 0; e < 4; e++) acc[i][j][e] = 0.0f;

    auto issue = [&](int it) {
        uint32_t base = smaddr(smg + (it & 1)*QSTG_W);
        int kg0 = it * 2;
#pragma unroll
        for (int i = 0; i < 4; i++) {
            int c = tid + i*128;
            int mloc = c >> 6, kgl = (c >> 5) & 1, lc = c & 31;
            CP16(base + c*16,
                 g_Ap + (((long)(mb0 + mloc)*64 + kg0 + kgl)*32 + lc)*4);
        }
        uint32_t baseB = base + 2048*4;
#pragma unroll
        for (int i = 0; i < 4; i++) {
            int c = tid + i*128;
            int jloc = c >> 6, kgl = (c >> 5) & 1, lc = c & 31;
            CP16(baseB + c*16,
                 Wp + (((long)(jp0 + jloc)*64 + kg0 + kgl)*32 + lc)*4);
        }
    };

    issue(0); CPCOMMIT();
    for (int it = 0; it < 32; ++it) {
        if (it + 1 < 32) issue(it + 1);
        CPCOMMIT();
        CPWAIT(1);
        __syncthreads();
        const uint32_t* As = smg + (it & 1)*QSTG_W;
        const uint32_t* Bs = As + 2048;
#pragma unroll
        for (int kgl = 0; kgl < 2; kgl++) {
            uint32_t a[4][4], b[4][4];
#pragma unroll
            for (int i = 0; i < 4; i++) {
                int mloc = (mw >> 4) + i;
                *(uint4*)a[i] = *(const uint4*)(As + ((mloc*2 + kgl)*32 + lane)*4);
            }
#pragma unroll
            for (int jp = 0; jp < 4; jp++) {
                int jloc = (nw >> 4) + jp;
                *(uint4*)b[jp] = *(const uint4*)(Bs + ((jloc*2 + kgl)*32 + lane)*4);
            }
#pragma unroll
            for (int i = 0; i < 4; i++)
#pragma unroll
                for (int jp = 0; jp < 4; jp++) {
                    mma16(acc[i][2*jp],     a[i][0], a[i][1], a[i][2], a[i][3],
                          b[jp][0], b[jp][1]);
                    mma16(acc[i][2*jp + 1], a[i][0], a[i][1], a[i][2], a[i][3],
                          b[jp][2], b[jp][3]);
                }
        }
        __syncthreads();
    }

    if (z < 2) {
        // Q/K epilogue: + bias, pack f16x2, store [token][dimpair]
        uint32_t* Og = (z == 0) ? g_Qh : g_Kh;
#pragma unroll
        for (int j = 0; j < 8; j++) {
            int col = col0 + nw + j*8 + 2*t;
            int colw = ((col0 + nw + j*8) >> 1) + t;
            float b0 = bias[col], b1 = bias[col + 1];
#pragma unroll
            for (int i = 0; i < 4; i++) {
                int row = row0 + mw + i*16 + g;
                Og[(long)row*W2R + colw]       = packh2(acc[i][j][0] + b0, acc[i][j][1] + b1);
                Og[(long)(row + 8)*W2R + colw] = packh2(acc[i][j][2] + b0, acc[i][j][3] + b1);
            }
        }
    } else {
        // V epilogue: stage [token_local][dimpair] in smem, write g_Vt
        uint32_t* sv = smg;                        // 128 x 65 words
#pragma unroll
        for (int j = 0; j < 8; j++) {
            int col = col0 + nw + j*8 + 2*t;
            int dpl = ((nw + j*8) >> 1) + t;       // local dim-pair 0..63
            float b0 = bias[col], b1 = bias[col + 1];
#pragma unroll
            for (int i = 0; i < 4; i++) {
                int tokl = mw + i*16 + g;
                sv[tokl*65 + dpl]       = packh2(acc[i][j][0] + b0, acc[i][j][1] + b1);
                sv[(tokl + 8)*65 + dpl] = packh2(acc[i][j][2] + b0, acc[i][j][3] + b1);
            }
        }
        __syncthreads();

        const int b = row0 >> 10;                  // batch
        const int t0 = row0 & 1023;                // token offset within batch
        const int bh = b*HH + blockIdx.x;          // col block == head
        uint32_t* dst = g_Vt + ((long)bh*DHH)*512 + (t0 >> 1);
#pragma unroll
        for (int i = 0; i < 64; i++) {
            int idx = tid + i*128;                 // 0..8191
            int dim = idx >> 6, tpl = idx & 63;
            uint32_t w0 = sv[(2*tpl)*65 + (dim >> 1)];
            uint32_t w1 = sv[(2*tpl + 1)*65 + (dim >> 1)];
            uint32_t o = (dim & 1) ? __byte_perm(w0, w1, 0x7632)
                                   : __byte_perm(w0, w1, 0x5410);
            dst[(long)dim*512 + tpl] = o;
        }
    }
}

// ---------------------------------------------------------------------------
// Pass 2: causal attention (unchanged from R11/R12, measured 89us).
// ---------------------------------------------------------------------------
#define KH_STR 68
#define VT_STR 36
#define KTILE_W (64*KH_STR)
#define VTILE_W (128*VT_STR)
#define STAGE_W (KTILE_W + VTILE_W)
#define ASM_BYTES (2*STAGE_W*4)           // 71,680 B per CTA

__global__ __launch_bounds__(128, 2)
void attn_kernel(float* __restrict__ out)
{
    extern __shared__ uint32_t sm[];

    const int tid = threadIdx.x;
    const int w = tid >> 5, lane = tid & 31;
    const int g = lane >> 2, t = lane & 3;
    const int m0 = w * 16;
    const int qt = 15 - blockIdx.x;
    const int q0 = qt * 64;
    const int bh = blockIdx.y, b = bh >> 3, h = bh & 7;
    const int nk = qt + 1;

    const uint32_t* Qg = g_Qh + (long)b*SS*W2R + h*64;
    const uint32_t* Kg = g_Kh + (long)b*SS*W2R + h*64;
    const uint32_t* Vtg = g_Vt + (long)bh*DHH*512;

    const uint32_t kOff = (uint32_t)((((lane >> 4)*8 + (lane & 7))*KH_STR)*4
                                     + ((lane >> 3) & 1)*16);
    const uint32_t vOff = (uint32_t)((((lane >> 4)*8 + (lane & 7))*VT_STR)*4
                                     + ((lane >> 3) & 1)*16);
    const uint32_t aOff = (uint32_t)(((m0 + (lane & 7) + ((lane >> 3) & 1)*8)*KH_STR)*4
                                     + (lane >> 4)*16);

    {
        uint32_t base = smaddr(sm);
#pragma unroll
        for (int i = 0; i < 8; i++) {
            int c = tid + i*128;
            int r = c >> 4, part = c & 15;
            CP16(base + (r*KH_STR + part*4)*4, Qg + (long)(q0 + r)*W2R + part*4);
        }
        CPCOMMIT(); CPWAIT(0);
    }
    __syncthreads();

    uint32_t aQ[8][4];
    {
        uint32_t baseA = smaddr(sm) + aOff;
#pragma unroll
        for (int K = 0; K < 8; K++)
            LDSM4(aQ[K][0], aQ[K][1], aQ[K][2], aQ[K][3], baseA + K*32);
    }
    __syncthreads();

    float accO[16][4];
#pragma unroll
    for (int j = 0; j < 16; j++)
#pragma unroll
        for (int e = 0; e < 4; e++) accO[j][e] = 0.0f;
    float l0 = 0.0f, l1 = 0.0f;
    const float scl = 0.08838834764831843f;
    const float LN16 = 2.772588722239781f;

    auto issue = [&](int kt) {
        uint32_t baseK = smaddr(sm + (kt & 1)*STAGE_W);
        uint32_t baseV = baseK + KTILE_W*4;
        int k0 = kt * 64;
#pragma unroll
        for (int i = 0; i < 8; i++) {
            int c = tid + i*128;
            int r = c >> 4, part = c & 15;
            CP16(baseK + (r*KH_STR + part*4)*4, Kg + (long)(k0 + r)*W2R + part*4);
        }
#pragma unroll
        for (int i = 0; i < 8; i++) {
            int c = tid + i*128;
            int dim = c >> 3, part = c & 7;
            CP16(baseV + (dim*VT_STR + part*4)*4,
                 Vtg + (long)dim*512 + kt*32 + part*4);
        }
    };

    issue(0); CPCOMMIT();
    for (int kt = 0; kt < nk; kt++) {
        if (kt + 1 < nk) issue(kt + 1);
        CPCOMMIT();
        CPWAIT(1);
        __syncthreads();
        const uint32_t stg = smaddr(sm + (kt & 1)*STAGE_W);
        const uint32_t kBase = stg + kOff;
        const uint32_t vBase = stg + KTILE_W*4 + vOff;
        const int k0 = kt * 64;

        float s[8][4];
#pragma unroll
        for (int j = 0; j < 8; j++)
#pragma unroll
            for (int e = 0; e < 4; e++) s[j][e] = 0.0f;
#pragma unroll
        for (int K = 0; K < 8; K++) {
#pragma unroll
            for (int jp2 = 0; jp2 < 4; jp2++) {
                uint32_t b0, b1, b2, b3;
                LDSM4(b0, b1, b2, b3, kBase + jp2*(16*KH_STR*4) + K*32);
                mma16(s[2*jp2],     aQ[K][0], aQ[K][1], aQ[K][2], aQ[K][3], b0, b1);
                mma16(s[2*jp2 + 1], aQ[K][0], aQ[K][1], aQ[K][2], aQ[K][3], b2, b3);
            }
        }

        const int row_g  = q0 + m0 + g;
        const int row_g8 = row_g + 8;
        const bool diag = (k0 + 63 > row_g);
#pragma unroll
        for (int j = 0; j < 8; j++) {
            int c0 = k0 + j*8 + 2*t;
            float y0 = __expf(s[j][0]*scl), y1 = __expf(s[j][1]*scl);
            float y2 = __expf(s[j][2]*scl), y3 = __expf(s[j][3]*scl);
            float p0 = __expf(y0 - LN16), p1 = __expf(y1 - LN16);
            float p2 = __expf(y2 - LN16), p3 = __expf(y3 - LN16);
            if (diag) {
                if (c0     > row_g ) p0 = 0.0f;
                if (c0 + 1 > row_g ) p1 = 0.0f;
                if (c0     > row_g8) p2 = 0.0f;
                if (c0 + 1 > row_g8) p3 = 0.0f;
            }
            l0 += p0 + p1;
            l1 += p2 + p3;
            s[j][0] = p0; s[j][1] = p1; s[j][2] = p2; s[j][3] = p3;
        }

#pragma unroll
        for (int J = 0; J < 4; J++) {
            uint32_t a0 = packh2(s[2*J][0],     s[2*J][1]);
            uint32_t a1 = packh2(s[2*J][2],     s[2*J][3]);
            uint32_t a2 = packh2(s[2*J + 1][0], s[2*J + 1][1]);
            uint32_t a3 = packh2(s[2*J + 1][2], s[2*J + 1][3]);
#pragma unroll
            for (int jbp = 0; jbp < 8; jbp++) {
                uint32_t b0, b1, b2, b3;
                LDSM4(b0, b1, b2, b3, vBase + jbp*(16*VT_STR*4) + J*32);
                mma16(accO[2*jbp],     a0, a1, a2, a3, b0, b1);
                mma16(accO[2*jbp + 1], a0, a1, a2, a3, b2, b3);
            }
        }
        __syncthreads();
    }

    l0 += __shfl_xor_sync(0xffffffffu, l0, 1);
    l0 += __shfl_xor_sync(0xffffffffu, l0, 2);
    l1 += __shfl_xor_sync(0xffffffffu, l1, 1);
    l1 += __shfl_xor_sync(0xffffffffu, l1, 2);
    const float r0 = 1.0f / l0, r1 = 1.0f / l1;

    float* outp = out + ((long)b*SS + q0 + m0 + g)*HIDD + h*DHH;
#pragma unroll
    for (int j = 0; j < 16; j++) {
        int col = j*8 + 2*t;
        *(float2*)(outp + col)          = make_float2(accO[j][0]*r0, accO[j][1]*r0);
        *(float2*)(outp + 8*HIDD + col) = make_float2(accO[j][2]*r1, accO[j][3]*r1);
    }
}

// ---------------------------------------------------------------------------
extern "C" void kernel_launch(void* const* d_in, const int* in_sizes, int n_in,
                              void* d_out, int out_size)
{
    const float* queries = (const float*)d_in[0];
    const float* Wq = (const float*)d_in[1];
    const float* bq = (const float*)d_in[2];
    const float* Wk = (const float*)d_in[3];
    const float* bk = (const float*)d_in[4];
    const float* Wv = (const float*)d_in[5];
    const float* bv = (const float*)d_in[6];
    float* out = (float*)d_out;

    cudaFuncSetAttribute(qkv_mma_kernel, cudaFuncAttributeMaxDynamicSharedMemorySize, GSM_BYTES);
    cudaFuncSetAttribute(attn_kernel, cudaFuncAttributeMaxDynamicSharedMemorySize, ASM_BYTES);

    prep_a_kernel<<<4096, 256>>>(queries);
    prep_w_kernel<<<dim3(512, 1, 3), 256>>>(Wq, Wk, Wv);
    qkv_mma_kernel<<<dim3(8, 64, 3), 128, GSM_BYTES>>>(bq, bk, bv);
    attn_kernel<<<dim3(16, 64), 128, ASM_BYTES>>>(out);
}